// round 12
// baseline (speedup 1.0000x reference)
#include <cuda_runtime.h>
#include <cuda_fp16.h>
#include <cstdint>
#include <cstddef>

#define BATCH 128
#define RR    196
#define ENCD  2048
#define ATTD  512
#define DECD  512
#define EMBD  512
#define VOC   10000
#define TSTEPS 20
#define NB    128          // megakernel blocks (co-resident: 1/SM on 148 SMs)

// ---------------- device scratch (static allocation only) ----------------
__device__ __half g_att1h[(size_t)BATCH * RR * ATTD];   // fp16 att1 (25.7 MB)
__device__ __half g_ench[(size_t)BATCH * RR * ENCD];    // fp16 mirror of enc (102.8 MB)
__device__ float g_mean[BATCH * ENCD];
__device__ float g_state[BATCH * 1024];            // [h | c]
__device__ float g_hproj[BATCH * 4608];            // [att2 | fbeta_pre | hWhh]
__device__ float g_ctx[BATCH * ENCD];
__device__ float g_gadd[BATCH * 2048];
__device__ float g_gpart[4 * BATCH * 2048];        // split-K partials for gates
__device__ float g_H[BATCH * TSTEPS * DECD];       // all h_t, row = b*TSTEPS+t
__device__ float g_E[BATCH * TSTEPS * EMBD];
__device__ float g_embproj[BATCH * TSTEPS * 2048];
__device__ float g_Wcat[4608 * 512];
__device__ float g_bcat[4608];
__device__ float g_bsum[2048];
__device__ float g_Winit[1024 * ENCD];
__device__ float g_binit[1024];
__device__ unsigned g_bar;                         // grid-barrier counter (memset per launch)

// ---------------- helpers ----------------
#define MMA_F16(c, a, b0, b1)                                               \
    asm volatile(                                                           \
        "mma.sync.aligned.m16n8k16.row.col.f32.f16.f16.f32 "                \
        "{%0,%1,%2,%3}, {%4,%5,%6,%7}, {%8,%9}, {%0,%1,%2,%3};"             \
        : "+f"(c[0]), "+f"(c[1]), "+f"(c[2]), "+f"(c[3])                    \
        : "r"(a[0]), "r"(a[1]), "r"(a[2]), "r"(a[3]), "r"(b0), "r"(b1))

__device__ __forceinline__ void cp_async16(uint32_t saddr, const void* gptr, int src_bytes) {
    asm volatile("cp.async.cg.shared.global [%0], [%1], 16, %2;\n"
                 :: "r"(saddr), "l"(gptr), "r"(src_bytes));
}
__device__ __forceinline__ void cp_commit() { asm volatile("cp.async.commit_group;\n"); }

__device__ __forceinline__ unsigned pack_h2(float2 p) {
    __half2 h = __float22half2_rn(p);
    return *(unsigned*)&h;
}

#define SROW 36

// ================= fp16 GEMM tile body (BM=128, 256 threads) =================
// Computes C tile [m0=0..128) x [n0, n0+BN) += A[:, Koff..Koff+K) @ B^T.
// Used both by the standalone kernel and the megakernel phases.
template <int BN, typename OutT>
__device__ __forceinline__ void gemm_tile_body(
    float* smem,
    const float* __restrict__ A, int lda,
    const float* __restrict__ Bm, int ldb,
    const float* __restrict__ bias,
    const float* __restrict__ Csrc, int ldsrc,
    OutT* __restrict__ C, int ldc,
    int m0, int n0, int N, int K, int Koff, bool final_z) {
    constexpr int STAGE_T = (128 + BN) * SROW;
    constexpr int NI = BN / 16;
    const int tid = threadIdx.x;
    const int warp = tid >> 5, lane = tid & 31;
    const int g = lane >> 2, tg = lane & 3;
    const int wm = (warp >> 1) * 32;
    const int wn = (warp & 1) * (BN / 2);

    float acc[2][NI][4];
#pragma unroll
    for (int mi = 0; mi < 2; mi++)
#pragma unroll
        for (int ni = 0; ni < NI; ni++)
#pragma unroll
            for (int j = 0; j < 4; j++) acc[mi][ni][j] = 0.f;

    const int ntiles = K >> 5;

    auto load_stage = [&](int buf, int kt) {
        float* sA = smem + buf * STAGE_T;
        float* sB = sA + 128 * SROW;
        const int kb = Koff + kt;
#pragma unroll
        for (int i = 0; i < 4; i++) {
            int idx = tid + i * 256;
            int row = idx >> 3;
            int q = (idx & 7) << 2;
            uint32_t d = (uint32_t)__cvta_generic_to_shared(sA + row * SROW + q);
            cp_async16(d, A + (size_t)(m0 + row) * lda + kb + q, 16);
        }
#pragma unroll
        for (int i = 0; i < BN / 32; i++) {
            int idx = tid + i * 256;
            int row = idx >> 3;
            int q = (idx & 7) << 2;
            int nr = n0 + row;
            int ok = (nr < N);
            if (!ok) nr = N - 1;
            uint32_t d = (uint32_t)__cvta_generic_to_shared(sB + row * SROW + q);
            cp_async16(d, Bm + (size_t)nr * ldb + kb + q, ok ? 16 : 0);
        }
        cp_commit();
    };

    load_stage(0, 0);

    for (int kt = 0; kt < ntiles; kt++) {
        if (kt + 1 < ntiles) {
            load_stage((kt + 1) & 1, (kt + 1) << 5);
            asm volatile("cp.async.wait_group 1;\n");
        } else {
            asm volatile("cp.async.wait_group 0;\n");
        }
        __syncthreads();

        const float* sA = smem + (kt & 1) * STAGE_T;
        const float* sB = sA + 128 * SROW;

#pragma unroll
        for (int ks = 0; ks < 2; ks++) {
            const int k0 = ks * 16;
            unsigned ah[2][4];
#pragma unroll
            for (int mi = 0; mi < 2; mi++) {
                int r = wm + mi * 16;
                ah[mi][0] = pack_h2(*(const float2*)&sA[(r + g) * SROW + k0 + 2 * tg]);
                ah[mi][1] = pack_h2(*(const float2*)&sA[(r + g + 8) * SROW + k0 + 2 * tg]);
                ah[mi][2] = pack_h2(*(const float2*)&sA[(r + g) * SROW + k0 + 8 + 2 * tg]);
                ah[mi][3] = pack_h2(*(const float2*)&sA[(r + g + 8) * SROW + k0 + 8 + 2 * tg]);
            }
#pragma unroll
            for (int ni = 0; ni < NI; ni++) {
                int cb = wn + ni * 8;
                unsigned b0 = pack_h2(*(const float2*)&sB[(cb + g) * SROW + k0 + 2 * tg]);
                unsigned b1 = pack_h2(*(const float2*)&sB[(cb + g) * SROW + k0 + 8 + 2 * tg]);
#pragma unroll
                for (int mi = 0; mi < 2; mi++) MMA_F16(acc[mi][ni], ah[mi], b0, b1);
            }
        }
        __syncthreads();
    }

#pragma unroll
    for (int mi = 0; mi < 2; mi++) {
#pragma unroll
        for (int ni = 0; ni < NI; ni++) {
            int r0 = m0 + wm + mi * 16 + g;
            int c0 = n0 + wn + ni * 8 + tg * 2;
#pragma unroll
            for (int half = 0; half < 2; half++) {
                int rr = r0 + half * 8;
#pragma unroll
                for (int j = 0; j < 2; j++) {
                    int cc = c0 + j;
                    if (cc >= N) continue;
                    float v = acc[mi][ni][half * 2 + j];
                    if (final_z) {
                        if (bias) v += bias[cc];
                        if (Csrc) v += Csrc[(size_t)rr * ldsrc + cc];
                    }
                    C[(size_t)rr * ldc + cc] = (OutT)v;
                }
            }
        }
    }
}

// standalone GEMM kernel (prologue + fc)
template <int BN, typename OutT>
__global__ void __launch_bounds__(256) gemm_f16(
    const float* __restrict__ A, int lda,
    const float* __restrict__ Bm, int ldb,
    const float* __restrict__ bias,
    const float* __restrict__ Csrc, int ldsrc,
    OutT* __restrict__ Cbase, int ldc, size_t zstride,
    int N, int K) {
    extern __shared__ float smem[];
    OutT* C = Cbase + (size_t)blockIdx.z * zstride;
    gemm_tile_body<BN, OutT>(smem, A, lda, Bm, ldb, bias, Csrc, ldsrc, C, ldc,
                             blockIdx.y * 128, blockIdx.x * BN, N, K,
                             blockIdx.z * K, gridDim.z == 1);
}

// ---------------- grid barrier (co-resident blocks only) ----------------
__device__ __forceinline__ void grid_barrier(unsigned target_arrivals) {
    __syncthreads();
    if (threadIdx.x == 0) {
        __threadfence();
        atomicAdd(&g_bar, 1u);
        while (*(volatile unsigned*)&g_bar < target_arrivals) __nanosleep(64);
    }
    __syncthreads();
    __threadfence();
}

// ================= persistent megakernel for the 20-step recurrence =================
__global__ void __launch_bounds__(256) loop_kernel(
    const __half* __restrict__ att1h, const __half* __restrict__ ench,
    float* __restrict__ state, float* __restrict__ hproj,
    const float* __restrict__ Wcat, const float* __restrict__ bcat,
    const float* __restrict__ wfull, const float* __restrict__ bfull,
    const float* __restrict__ embproj,
    float* __restrict__ ctx, float* __restrict__ gadd, float* __restrict__ gpart,
    const float* __restrict__ W_ih, float* __restrict__ Hbuf,
    float* __restrict__ out_alpha) {
    extern __shared__ float sm[];
    const int bid = blockIdx.x;
    const int tid = threadIdx.x;
    const int warp = tid >> 5, lane = tid & 31;
    unsigned epoch = 0;

    for (int t = 0; t < TSTEPS; t++) {
        // ---- phase 1: hproj = h @ Wcat^T + bcat  (72 tiles of BN=64) ----
        if (bid < 72)
            gemm_tile_body<64, float>(sm, state, 1024, Wcat, 512, bcat, nullptr, 0,
                                      hproj, 4608, 0, bid * 64, 4608, 512, 0, true);
        grid_barrier(++epoch * NB);

        // ---- phase 2: attention + softmax + context + gadd (block = batch row) ----
        {
            const int b = bid;
            float* s_att2 = sm;            // 512
            float* s_wf   = sm + 512;      // 512
            float* s_sc   = sm + 1024;     // 196 (pad to 208)
            float* s_red  = sm + 1232;     // 8
            for (int i = tid; i < 512; i += 256) {
                s_att2[i] = hproj[b * 4608 + i];
                s_wf[i] = wfull[i];
            }
            __syncthreads();

            float bf = bfull[0];
            // scores: warp handles row pair (r, r+8) for 4x loads in flight
            for (int r0 = warp; r0 < RR; r0 += 16) {
                int r1 = r0 + 8;
                bool has1 = (r1 < RR);
                const float4* ap0 = (const float4*)(att1h + (size_t)(b * RR + r0) * ATTD);
                const float4* ap1 = (const float4*)(att1h + (size_t)(b * RR + (has1 ? r1 : r0)) * ATTD);
                float4 v[4];
                v[0] = ap0[lane]; v[1] = ap0[lane + 32];
                v[2] = ap1[lane]; v[3] = ap1[lane + 32];
                float s0 = 0.f, s1 = 0.f;
#pragma unroll
                for (int i = 0; i < 2; i++) {
                    const __half2* hv = (const __half2*)&v[i];
                    int a = (lane + i * 32) * 8;
#pragma unroll
                    for (int j = 0; j < 4; j++) {
                        float2 f = __half22float2(hv[j]);
                        s0 += fmaxf(f.x + s_att2[a + 2 * j], 0.f) * s_wf[a + 2 * j]
                            + fmaxf(f.y + s_att2[a + 2 * j + 1], 0.f) * s_wf[a + 2 * j + 1];
                    }
                }
#pragma unroll
                for (int i = 2; i < 4; i++) {
                    const __half2* hv = (const __half2*)&v[i];
                    int a = (lane + (i - 2) * 32) * 8;
#pragma unroll
                    for (int j = 0; j < 4; j++) {
                        float2 f = __half22float2(hv[j]);
                        s1 += fmaxf(f.x + s_att2[a + 2 * j], 0.f) * s_wf[a + 2 * j]
                            + fmaxf(f.y + s_att2[a + 2 * j + 1], 0.f) * s_wf[a + 2 * j + 1];
                    }
                }
#pragma unroll
                for (int o = 16; o; o >>= 1) {
                    s0 += __shfl_xor_sync(0xffffffffu, s0, o);
                    s1 += __shfl_xor_sync(0xffffffffu, s1, o);
                }
                if (lane == 0) {
                    s_sc[r0] = s0 + bf;
                    if (has1) s_sc[r1] = s1 + bf;
                }
            }
            __syncthreads();

            // softmax over 196 (threads 0..195)
            float m = (tid < RR) ? s_sc[tid] : -1e30f;
#pragma unroll
            for (int o = 16; o; o >>= 1) m = fmaxf(m, __shfl_xor_sync(0xffffffffu, m, o));
            if (lane == 0) s_red[warp] = m;
            __syncthreads();
            m = s_red[0];
#pragma unroll
            for (int w = 1; w < 8; w++) m = fmaxf(m, s_red[w]);
            __syncthreads();
            float sum = 0.f;
            if (tid < RR) {
                float e = expf(s_sc[tid] - m);
                s_sc[tid] = e;
                sum = e;
            }
#pragma unroll
            for (int o = 16; o; o >>= 1) sum += __shfl_xor_sync(0xffffffffu, sum, o);
            if (lane == 0) s_red[warp] = sum;
            __syncthreads();
            sum = 0.f;
#pragma unroll
            for (int w = 0; w < 8; w++) sum += s_red[w];
            float inv = 1.f / sum;
            if (tid < RR) out_alpha[((size_t)b * TSTEPS + t) * RR + tid] = s_sc[tid] * inv;
            __syncthreads();

            // context: thread handles 8 columns [tid*8, tid*8+8), r unrolled x8
            {
                const float4* ep4 = (const float4*)(ench + (size_t)b * RR * ENCD) + tid;
                float a8[8];
#pragma unroll
                for (int j = 0; j < 8; j++) a8[j] = 0.f;
#pragma unroll 8
                for (int r = 0; r < RR; r++) {
                    float4 v = ep4[(size_t)r * 256];
                    const __half2* hv = (const __half2*)&v;
                    float a = s_sc[r];
#pragma unroll
                    for (int j = 0; j < 4; j++) {
                        float2 f = __half22float2(hv[j]);
                        a8[2 * j] += a * f.x;
                        a8[2 * j + 1] += a * f.y;
                    }
                }
                const float* ebp = embproj + ((size_t)b * TSTEPS + t) * 2048;
#pragma unroll
                for (int j = 0; j < 8; j++) {
                    int e = tid * 8 + j;
                    float gp = hproj[b * 4608 + 512 + e];
                    ctx[b * ENCD + e] = (a8[j] * inv) / (1.f + expf(-gp));
                    gadd[b * 2048 + e] = ebp[e] + hproj[b * 4608 + 2560 + e];
                }
            }
        }
        grid_barrier(++epoch * NB);

        // ---- phase 3: gates partials = ctx @ W_ih[:,512:]^T (32 n-tiles x 4 k-slices) ----
        {
            int n0 = (bid & 31) * 64;
            int z = bid >> 5;
            gemm_tile_body<64, float>(sm, ctx, ENCD, W_ih + 512, EMBD + ENCD, nullptr,
                                      nullptr, 0, gpart + (size_t)z * BATCH * 2048, 2048,
                                      0, n0, 2048, 512, z * 512, false);
        }
        grid_barrier(++epoch * NB);

        // ---- phase 4: LSTM pointwise (block = batch row, 2 d per thread) ----
        {
            const int b = bid;
#pragma unroll
            for (int dd = 0; dd < 2; dd++) {
                int d = tid + dd * 256;
                float gt[4];
#pragma unroll
                for (int q = 0; q < 4; q++) {
                    int j = b * 2048 + q * 512 + d;
                    float s = gadd[j];
#pragma unroll
                    for (int z = 0; z < 4; z++) s += gpart[(size_t)z * BATCH * 2048 + j];
                    gt[q] = s;
                }
                float i_ = 1.f / (1.f + expf(-gt[0]));
                float f_ = 1.f / (1.f + expf(-gt[1]));
                float g_ = tanhf(gt[2]);
                float o_ = 1.f / (1.f + expf(-gt[3]));
                float c = state[b * 1024 + 512 + d];
                float cn = f_ * c + i_ * g_;
                float hn = o_ * tanhf(cn);
                state[b * 1024 + d] = hn;
                state[b * 1024 + 512 + d] = cn;
                Hbuf[((size_t)b * TSTEPS + t) * DECD + d] = hn;
            }
        }
        grid_barrier(++epoch * NB);
    }
}

// ---------------- small kernels ----------------
__global__ void bsum_kernel(float* __restrict__ out, const float* __restrict__ a,
                            const float* __restrict__ b) {
    int i = blockIdx.x * blockDim.x + threadIdx.x;
    if (i < 2048) out[i] = a[i] + b[i];
}

__global__ void gather_kernel(const int* __restrict__ cap, const float* __restrict__ table,
                              float* __restrict__ E) {
    int bt = blockIdx.x;
    int b = bt / TSTEPS, tt = bt % TSTEPS;
    int idx = cap[b * (TSTEPS + 1) + tt];
    const float4* src = (const float4*)(table + (size_t)idx * EMBD);
    float4* dst = (float4*)(E + (size_t)bt * EMBD);
    dst[threadIdx.x] = src[threadIdx.x];
}

__global__ void prep_enc_kernel(const float* __restrict__ enc, __half* __restrict__ ench,
                                float* __restrict__ mean) {
    int b = blockIdx.y;
    int e = blockIdx.x * 256 + threadIdx.x;
    const float* ep = enc + (size_t)b * RR * ENCD + e;
    __half* op = ench + (size_t)b * RR * ENCD + e;
    float acc = 0.f;
#pragma unroll 4
    for (int r = 0; r < RR; r++) {
        float v = ep[(size_t)r * ENCD];
        acc += v;
        op[(size_t)r * ENCD] = __float2half_rn(v);
    }
    mean[b * ENCD + e] = acc * (1.f / (float)RR);
}

// ---------------- host ----------------
static float* symaddr(const void* sym) {
    void* p = nullptr;
    cudaGetSymbolAddress(&p, sym);
    return (float*)p;
}

static const int SMEM64 = 2 * (192 * SROW) * 4;    // 55296
static const int SMEM128 = 2 * (256 * SROW) * 4;   // 73728

template <int BN, typename OutT>
static void launch_f16(const float* A, int lda, const float* B, int ldb,
                       const float* bias, const float* Csrc, int ldsrc,
                       OutT* C, int ldc, size_t zstride,
                       int M, int N, int K, int zsplit) {
    dim3 grid((N + BN - 1) / BN, M / 128, zsplit);
    int smem = (BN == 64) ? SMEM64 : SMEM128;
    gemm_f16<BN, OutT><<<grid, 256, smem>>>(A, lda, B, ldb, bias, Csrc, ldsrc, C, ldc,
                                            zstride, N, K / zsplit);
}

extern "C" void kernel_launch(void* const* d_in, const int* in_sizes, int n_in,
                              void* d_out, int out_size) {
    const float* enc       = (const float*)d_in[0];
    const int*   captions  = (const int*)d_in[1];
    const float* W_enc_att = (const float*)d_in[2];
    const float* b_enc_att = (const float*)d_in[3];
    const float* W_dec_att = (const float*)d_in[4];
    const float* b_dec_att = (const float*)d_in[5];
    const float* W_full    = (const float*)d_in[6];
    const float* b_full    = (const float*)d_in[7];
    const float* emb_table = (const float*)d_in[8];
    const float* W_ih      = (const float*)d_in[9];
    const float* W_hh      = (const float*)d_in[10];
    const float* b_ih      = (const float*)d_in[11];
    const float* b_hh      = (const float*)d_in[12];
    const float* W_init_h  = (const float*)d_in[13];
    const float* b_init_h  = (const float*)d_in[14];
    const float* W_init_c  = (const float*)d_in[15];
    const float* b_init_c  = (const float*)d_in[16];
    const float* W_fbeta   = (const float*)d_in[17];
    const float* b_fbeta   = (const float*)d_in[18];
    const float* W_fc      = (const float*)d_in[19];
    const float* b_fc      = (const float*)d_in[20];

    float* out_pred  = (float*)d_out;
    float* out_alpha = out_pred + (size_t)BATCH * TSTEPS * VOC;

    __half* att1h = (__half*)symaddr(g_att1h);
    __half* ench  = (__half*)symaddr(g_ench);
    float* meanb  = symaddr(g_mean);
    float* state  = symaddr(g_state);
    float* hproj  = symaddr(g_hproj);
    float* ctx    = symaddr(g_ctx);
    float* gadd   = symaddr(g_gadd);
    float* gpart  = symaddr(g_gpart);
    float* Hbuf   = symaddr(g_H);
    float* E      = symaddr(g_E);
    float* embprj = symaddr(g_embproj);
    float* Wcat   = symaddr(g_Wcat);
    float* bcat   = symaddr(g_bcat);
    float* bsum   = symaddr(g_bsum);
    float* Winit  = symaddr(g_Winit);
    float* binit  = symaddr(g_binit);
    void* barp = nullptr;
    cudaGetSymbolAddress(&barp, g_bar);

    cudaFuncSetAttribute(gemm_f16<64, float>, cudaFuncAttributeMaxDynamicSharedMemorySize, SMEM64);
    cudaFuncSetAttribute(gemm_f16<128, float>, cudaFuncAttributeMaxDynamicSharedMemorySize, SMEM128);
    cudaFuncSetAttribute(gemm_f16<128, __half>, cudaFuncAttributeMaxDynamicSharedMemorySize, SMEM128);
    cudaFuncSetAttribute(loop_kernel, cudaFuncAttributeMaxDynamicSharedMemorySize, SMEM64);

    // ---- prologue: weight concats ----
    cudaMemcpyAsync(Wcat, W_dec_att, (size_t)512 * 512 * 4, cudaMemcpyDeviceToDevice, 0);
    cudaMemcpyAsync(Wcat + 512 * 512, W_fbeta, (size_t)2048 * 512 * 4, cudaMemcpyDeviceToDevice, 0);
    cudaMemcpyAsync(Wcat + 2560 * 512, W_hh, (size_t)2048 * 512 * 4, cudaMemcpyDeviceToDevice, 0);
    cudaMemcpyAsync(bcat, b_dec_att, 512 * 4, cudaMemcpyDeviceToDevice, 0);
    cudaMemcpyAsync(bcat + 512, b_fbeta, 2048 * 4, cudaMemcpyDeviceToDevice, 0);
    cudaMemsetAsync(bcat + 2560, 0, 2048 * 4, 0);
    cudaMemcpyAsync(Winit, W_init_h, (size_t)512 * 2048 * 4, cudaMemcpyDeviceToDevice, 0);
    cudaMemcpyAsync(Winit + (size_t)512 * 2048, W_init_c, (size_t)512 * 2048 * 4,
                    cudaMemcpyDeviceToDevice, 0);
    cudaMemcpyAsync(binit, b_init_h, 512 * 4, cudaMemcpyDeviceToDevice, 0);
    cudaMemcpyAsync(binit + 512, b_init_c, 512 * 4, cudaMemcpyDeviceToDevice, 0);
    cudaMemsetAsync(barp, 0, 4, 0);

    bsum_kernel<<<8, 256>>>(bsum, b_ih, b_hh);
    prep_enc_kernel<<<dim3(8, BATCH), 256>>>(enc, ench, meanb);
    // state = mean @ [W_init_h; W_init_c]^T + [b_init_h; b_init_c]
    launch_f16<64, float>(meanb, ENCD, Winit, ENCD, binit, nullptr, 0, state, 1024, 0,
                          BATCH, 1024, ENCD, 1);
    gather_kernel<<<BATCH * TSTEPS, 128>>>(captions, emb_table, E);
    // embproj (all t): E @ W_ih[:, :512]^T + (b_ih + b_hh)
    launch_f16<128, float>(E, EMBD, W_ih, EMBD + ENCD, bsum, nullptr, 0, embprj, 2048, 0,
                           BATCH * TSTEPS, 2048, EMBD, 1);
    // att1 = enc @ W_enc_att^T + b_enc_att (fp16 output)
    launch_f16<128, __half>(enc, ENCD, W_enc_att, ENCD, b_enc_att, nullptr, 0, att1h, ATTD, 0,
                            BATCH * RR, ATTD, ENCD, 1);

    // ---- recurrence: ONE persistent kernel, software grid barriers ----
    loop_kernel<<<NB, 256, SMEM64>>>(att1h, ench, state, hproj, Wcat, bcat,
                                     W_full, b_full, embprj, ctx, gadd, gpart,
                                     W_ih, Hbuf, out_alpha);

    // ---- batched fc: preds[b,t,:] = h_t @ W_fc^T + b_fc ----
    launch_f16<128, float>(Hbuf, DECD, W_fc, DECD, b_fc, nullptr, 0, out_pred, VOC, 0,
                           BATCH * TSTEPS, VOC, DECD, 1);
}

// round 13
// speedup vs baseline: 1.0087x; 1.0087x over previous
#include <cuda_runtime.h>
#include <cuda_fp16.h>
#include <cstdint>
#include <cstddef>

#define BATCH 128
#define RR    196
#define ENCD  2048
#define ATTD  512
#define DECD  512
#define EMBD  512
#define VOC   10000
#define TSTEPS 20
#define NB    128

#define SROW 36      // float smem row stride (floats)
#define HROW 40      // half smem row stride (halves) — conflict-free (stride 20 u32)

// ---------------- device scratch (static allocation only) ----------------
__device__ __half g_att1h[(size_t)BATCH * RR * ATTD];
__device__ __half g_ench[(size_t)BATCH * RR * ENCD];
__device__ float g_mean[BATCH * ENCD];
__device__ float g_state[BATCH * 1024];            // [h | c]
__device__ float g_hproj[BATCH * 4608];            // [att2 | fbeta_pre | hWhh]
__device__ float g_ctx[BATCH * ENCD];
__device__ float g_gadd[BATCH * 2048];
__device__ float g_gpart[4 * BATCH * 2048];
__device__ __half g_Hh[(size_t)BATCH * TSTEPS * DECD];   // fp16 h_t for fc
__device__ float g_E[BATCH * TSTEPS * EMBD];
__device__ float g_embproj[BATCH * TSTEPS * 2048];
__device__ float g_Wcat[4608 * 512];
__device__ float g_bcat[4608];
__device__ float g_bsum[2048];
__device__ float g_Winit[1024 * ENCD];
__device__ float g_binit[1024];
__device__ unsigned g_bars[8 * 32];                // 8 counters, 128B apart

// ---------------- helpers ----------------
#define MMA_F16(c, a, b0, b1)                                               \
    asm volatile(                                                           \
        "mma.sync.aligned.m16n8k16.row.col.f32.f16.f16.f32 "                \
        "{%0,%1,%2,%3}, {%4,%5,%6,%7}, {%8,%9}, {%0,%1,%2,%3};"             \
        : "+f"(c[0]), "+f"(c[1]), "+f"(c[2]), "+f"(c[3])                    \
        : "r"(a[0]), "r"(a[1]), "r"(a[2]), "r"(a[3]), "r"(b0), "r"(b1))

__device__ __forceinline__ void cp_async16(uint32_t saddr, const void* gptr) {
    asm volatile("cp.async.cg.shared.global [%0], [%1], 16;\n" :: "r"(saddr), "l"(gptr));
}
__device__ __forceinline__ void cp_commit() { asm volatile("cp.async.commit_group;\n"); }

__device__ __forceinline__ unsigned pack_h2(float2 p) {
    __half2 h = __float22half2_rn(p);
    return *(unsigned*)&h;
}

static constexpr int stage_b(int BN, int asz) {
    return 128 * ((asz == 2) ? HROW : SROW) * asz + BN * SROW * 4;
}

// ================= unified fp16 GEMM tile body (256 threads) =================
template <int BN, typename AT, typename OutT>
__device__ __forceinline__ void gemm_tile_body(
    char* smem,
    const AT* __restrict__ A, int lda,
    const float* __restrict__ Bm, int ldb,
    const float* __restrict__ bias,
    const float* __restrict__ Csrc, int ldsrc,
    OutT* __restrict__ C, int ldc,
    int m0, int n0, int N, int K, int Koff, bool final_z) {
    constexpr bool AH = (sizeof(AT) == 2);
    constexpr int ABYTES = 128 * (AH ? HROW : SROW) * (int)sizeof(AT);
    constexpr int STB = ABYTES + BN * SROW * 4;
    constexpr int NI = BN / 16;
    const int tid = threadIdx.x;
    const int warp = tid >> 5, lane = tid & 31;
    const int g = lane >> 2, tg = lane & 3;
    const int wm = (warp >> 1) * 32;
    const int wn = (warp & 1) * (BN / 2);

    float acc[2][NI][4];
#pragma unroll
    for (int mi = 0; mi < 2; mi++)
#pragma unroll
        for (int ni = 0; ni < NI; ni++)
#pragma unroll
            for (int j = 0; j < 4; j++) acc[mi][ni][j] = 0.f;

    const int ntiles = K >> 5;

    auto load_stage = [&](int buf, int kt) {
        char* base = smem + buf * STB;
        const int kb = Koff + kt;
        if (AH) {
            __half* sA = (__half*)base;
#pragma unroll
            for (int i = 0; i < 2; i++) {
                int idx = tid + i * 256;          // 0..511
                int row = idx >> 2;
                int q = (idx & 3) * 8;
                uint32_t d = (uint32_t)__cvta_generic_to_shared(sA + row * HROW + q);
                cp_async16(d, (const __half*)A + (size_t)(m0 + row) * lda + kb + q);
            }
        } else {
            float* sA = (float*)base;
#pragma unroll
            for (int i = 0; i < 4; i++) {
                int idx = tid + i * 256;
                int row = idx >> 3;
                int q = (idx & 7) << 2;
                uint32_t d = (uint32_t)__cvta_generic_to_shared(sA + row * SROW + q);
                cp_async16(d, (const float*)A + (size_t)(m0 + row) * lda + kb + q);
            }
        }
        float* sB = (float*)(base + ABYTES);
#pragma unroll
        for (int i = 0; i < BN / 32; i++) {
            int idx = tid + i * 256;
            int row = idx >> 3;
            int q = (idx & 7) << 2;
            int nr = n0 + row;
            if (nr >= N) nr = N - 1;
            uint32_t d = (uint32_t)__cvta_generic_to_shared(sB + row * SROW + q);
            cp_async16(d, Bm + (size_t)nr * ldb + kb + q);
        }
        cp_commit();
    };

    load_stage(0, 0);

    for (int kt = 0; kt < ntiles; kt++) {
        if (kt + 1 < ntiles) {
            load_stage((kt + 1) & 1, (kt + 1) << 5);
            asm volatile("cp.async.wait_group 1;\n");
        } else {
            asm volatile("cp.async.wait_group 0;\n");
        }
        __syncthreads();

        const char* base = smem + (kt & 1) * STB;
        const float* sB = (const float*)(base + ABYTES);

#pragma unroll
        for (int ks = 0; ks < 2; ks++) {
            const int k0 = ks * 16;
            unsigned ah[2][4];
            if (AH) {
                const __half* sAh = (const __half*)base;
#pragma unroll
                for (int mi = 0; mi < 2; mi++) {
                    int r = wm + mi * 16;
                    ah[mi][0] = *(const unsigned*)&sAh[(r + g) * HROW + k0 + 2 * tg];
                    ah[mi][1] = *(const unsigned*)&sAh[(r + g + 8) * HROW + k0 + 2 * tg];
                    ah[mi][2] = *(const unsigned*)&sAh[(r + g) * HROW + k0 + 8 + 2 * tg];
                    ah[mi][3] = *(const unsigned*)&sAh[(r + g + 8) * HROW + k0 + 8 + 2 * tg];
                }
            } else {
                const float* sAf = (const float*)base;
#pragma unroll
                for (int mi = 0; mi < 2; mi++) {
                    int r = wm + mi * 16;
                    ah[mi][0] = pack_h2(*(const float2*)&sAf[(r + g) * SROW + k0 + 2 * tg]);
                    ah[mi][1] = pack_h2(*(const float2*)&sAf[(r + g + 8) * SROW + k0 + 2 * tg]);
                    ah[mi][2] = pack_h2(*(const float2*)&sAf[(r + g) * SROW + k0 + 8 + 2 * tg]);
                    ah[mi][3] = pack_h2(*(const float2*)&sAf[(r + g + 8) * SROW + k0 + 8 + 2 * tg]);
                }
            }
#pragma unroll
            for (int ni = 0; ni < NI; ni++) {
                int cb = wn + ni * 8;
                unsigned b0 = pack_h2(*(const float2*)&sB[(cb + g) * SROW + k0 + 2 * tg]);
                unsigned b1 = pack_h2(*(const float2*)&sB[(cb + g) * SROW + k0 + 8 + 2 * tg]);
#pragma unroll
                for (int mi = 0; mi < 2; mi++) MMA_F16(acc[mi][ni], ah[mi], b0, b1);
            }
        }
        __syncthreads();
    }

#pragma unroll
    for (int mi = 0; mi < 2; mi++) {
#pragma unroll
        for (int ni = 0; ni < NI; ni++) {
            int r0 = m0 + wm + mi * 16 + g;
            int c0 = n0 + wn + ni * 8 + tg * 2;
#pragma unroll
            for (int half = 0; half < 2; half++) {
                int rr = r0 + half * 8;
#pragma unroll
                for (int j = 0; j < 2; j++) {
                    int cc = c0 + j;
                    if (cc >= N) continue;
                    float v = acc[mi][ni][half * 2 + j];
                    if (final_z) {
                        if (bias) v += bias[cc];
                        if (Csrc) v += Csrc[(size_t)rr * ldsrc + cc];
                    }
                    C[(size_t)rr * ldc + cc] = (OutT)v;
                }
            }
        }
    }
}

template <int BN, typename AT, typename OutT>
__global__ void __launch_bounds__(256) gemm_f16(
    const AT* __restrict__ A, int lda, const float* __restrict__ Bm, int ldb,
    const float* __restrict__ bias, const float* __restrict__ Csrc, int ldsrc,
    OutT* __restrict__ Cbase, int ldc, size_t zstride, int N, int K) {
    extern __shared__ char smem_raw[];
    OutT* C = Cbase + (size_t)blockIdx.z * zstride;
    gemm_tile_body<BN, AT, OutT>(smem_raw, A, lda, Bm, ldb, bias, Csrc, ldsrc, C, ldc,
                                 blockIdx.y * 128, blockIdx.x * BN, N, K,
                                 blockIdx.z * K, gridDim.z == 1);
}

// ================= 1024-thread GEMM body (megakernel, BM=128, BN=64, A f32) ==========
__device__ __forceinline__ void gemm64_1024(
    char* smem, const float* __restrict__ A, int lda,
    const float* __restrict__ Bm, int ldb, const float* __restrict__ bias,
    float* __restrict__ C, int ldc, int n0, int K, int Koff, bool add_bias) {
    constexpr int STB = (128 + 64) * SROW * 4;
    const int tid = threadIdx.x;     // 1024
    const int warp = tid >> 5, lane = tid & 31;
    const int g = lane >> 2, tg = lane & 3;
    const int wm = (warp >> 2) * 16;   // 8 m-groups
    const int wn = (warp & 3) * 16;    // 4 n-groups
    float acc[2][4];
#pragma unroll
    for (int ni = 0; ni < 2; ni++)
#pragma unroll
        for (int j = 0; j < 4; j++) acc[ni][j] = 0.f;

    const int ntiles = K >> 5;

    auto load_stage = [&](int buf, int kt) {
        float* sA = (float*)(smem + buf * STB);
        float* sB = sA + 128 * SROW;
        const int kb = Koff + kt;
        {
            int row = tid >> 3;         // 0..127
            int q = (tid & 7) << 2;
            uint32_t d = (uint32_t)__cvta_generic_to_shared(sA + row * SROW + q);
            cp_async16(d, A + (size_t)row * lda + kb + q);
        }
        if (tid < 512) {
            int row = tid >> 3;         // 0..63
            int q = (tid & 7) << 2;
            uint32_t d = (uint32_t)__cvta_generic_to_shared(sB + row * SROW + q);
            cp_async16(d, Bm + (size_t)(n0 + row) * ldb + kb + q);
        }
        cp_commit();
    };

    load_stage(0, 0);

    for (int kt = 0; kt < ntiles; kt++) {
        if (kt + 1 < ntiles) {
            load_stage((kt + 1) & 1, (kt + 1) << 5);
            asm volatile("cp.async.wait_group 1;\n");
        } else {
            asm volatile("cp.async.wait_group 0;\n");
        }
        __syncthreads();

        const float* sA = (const float*)(smem + (kt & 1) * STB);
        const float* sB = sA + 128 * SROW;

#pragma unroll
        for (int ks = 0; ks < 2; ks++) {
            const int k0 = ks * 16;
            unsigned ah[4];
            ah[0] = pack_h2(*(const float2*)&sA[(wm + g) * SROW + k0 + 2 * tg]);
            ah[1] = pack_h2(*(const float2*)&sA[(wm + g + 8) * SROW + k0 + 2 * tg]);
            ah[2] = pack_h2(*(const float2*)&sA[(wm + g) * SROW + k0 + 8 + 2 * tg]);
            ah[3] = pack_h2(*(const float2*)&sA[(wm + g + 8) * SROW + k0 + 8 + 2 * tg]);
#pragma unroll
            for (int ni = 0; ni < 2; ni++) {
                int cb = wn + ni * 8;
                unsigned b0 = pack_h2(*(const float2*)&sB[(cb + g) * SROW + k0 + 2 * tg]);
                unsigned b1 = pack_h2(*(const float2*)&sB[(cb + g) * SROW + k0 + 8 + 2 * tg]);
                MMA_F16(acc[ni], ah, b0, b1);
            }
        }
        __syncthreads();
    }

#pragma unroll
    for (int ni = 0; ni < 2; ni++) {
        int r0 = wm + g;
        int c0 = n0 + wn + ni * 8 + tg * 2;
#pragma unroll
        for (int half = 0; half < 2; half++) {
            int rr = r0 + half * 8;
#pragma unroll
            for (int j = 0; j < 2; j++) {
                int cc = c0 + j;
                float v = acc[ni][half * 2 + j];
                if (add_bias) v += bias[cc];
                C[(size_t)rr * ldc + cc] = v;
            }
        }
    }
}

// ---------------- distributed grid barrier ----------------
__device__ __forceinline__ void grid_barrier(unsigned target) {
    __syncthreads();
    if (threadIdx.x == 0) {
        __threadfence();
        atomicAdd(&g_bars[(blockIdx.x & 7) * 32], 1u);
        for (;;) {
            unsigned s = 0;
#pragma unroll
            for (int i = 0; i < 8; i++) s += *(volatile unsigned*)&g_bars[i * 32];
            if (s >= target) break;
            __nanosleep(64);
        }
    }
    __syncthreads();
    __threadfence();
}

// ================= persistent megakernel (128 blocks x 1024 threads) =================
__global__ void __launch_bounds__(1024) loop_kernel(
    const __half* __restrict__ att1h, const __half* __restrict__ ench,
    float* __restrict__ state, float* __restrict__ hproj,
    const float* __restrict__ Wcat, const float* __restrict__ bcat,
    const float* __restrict__ wfull, const float* __restrict__ bfull,
    const float* __restrict__ embproj,
    float* __restrict__ ctx, float* __restrict__ gadd, float* __restrict__ gpart,
    const float* __restrict__ W_ih, __half* __restrict__ Hh,
    float* __restrict__ out_alpha) {
    extern __shared__ char smem_raw[];
    float* sm = (float*)smem_raw;
    const int bid = blockIdx.x;
    const int tid = threadIdx.x;
    const int warp = tid >> 5, lane = tid & 31;
    unsigned epoch = 0;

    for (int t = 0; t < TSTEPS; t++) {
        // ---- phase 1: hproj = h @ Wcat^T + bcat (72 tiles) ----
        if (bid < 72)
            gemm64_1024(smem_raw, state, 1024, Wcat, 512, bcat, hproj, 4608,
                        bid * 64, 512, 0, true);
        grid_barrier(++epoch * NB);

        // ---- phase 2: attention + softmax + context + gadd (block = batch row) ----
        {
            const int b = bid;
            float* s_att2 = sm;                  // 512
            float* s_wf   = sm + 512;            // 512
            float* s_sc   = sm + 1024;           // 208
            float* s_red  = sm + 1232;           // 32
            float* s_part = sm + 1264;           // 4 * 2048
            if (tid < 512) {
                s_att2[tid] = hproj[b * 4608 + tid];
                s_wf[tid] = wfull[tid];
            }
            __syncthreads();

            float bf = bfull[0];
            for (int r = warp; r < RR; r += 32) {
                const float4* ap = (const float4*)(att1h + (size_t)(b * RR + r) * ATTD);
                float s = 0.f;
#pragma unroll
                for (int i = 0; i < 2; i++) {
                    float4 v = ap[lane + i * 32];
                    const __half2* hv = (const __half2*)&v;
                    int a = (lane + i * 32) * 8;
#pragma unroll
                    for (int j = 0; j < 4; j++) {
                        float2 f = __half22float2(hv[j]);
                        s += fmaxf(f.x + s_att2[a + 2 * j], 0.f) * s_wf[a + 2 * j]
                           + fmaxf(f.y + s_att2[a + 2 * j + 1], 0.f) * s_wf[a + 2 * j + 1];
                    }
                }
#pragma unroll
                for (int o = 16; o; o >>= 1) s += __shfl_xor_sync(0xffffffffu, s, o);
                if (lane == 0) s_sc[r] = s + bf;
            }
            __syncthreads();

            float m = (tid < RR) ? s_sc[tid] : -1e30f;
#pragma unroll
            for (int o = 16; o; o >>= 1) m = fmaxf(m, __shfl_xor_sync(0xffffffffu, m, o));
            if (lane == 0) s_red[warp] = m;
            __syncthreads();
            m = s_red[0];
#pragma unroll
            for (int w = 1; w < 32; w++) m = fmaxf(m, s_red[w]);
            __syncthreads();
            float sum = 0.f;
            if (tid < RR) {
                float e = expf(s_sc[tid] - m);
                s_sc[tid] = e;
                sum = e;
            }
#pragma unroll
            for (int o = 16; o; o >>= 1) sum += __shfl_xor_sync(0xffffffffu, sum, o);
            if (lane == 0) s_red[warp] = sum;
            __syncthreads();
            sum = 0.f;
#pragma unroll
            for (int w = 0; w < 32; w++) sum += s_red[w];
            float inv = 1.f / sum;
            if (tid < RR) out_alpha[((size_t)b * TSTEPS + t) * RR + tid] = s_sc[tid] * inv;
            __syncthreads();

            // context: 4 row-groups x 256 e-threads, float4 (8 halves) per row
            {
                int rg = tid >> 8;
                int et = tid & 255;
                const float4* ep4 = (const float4*)(ench + (size_t)b * RR * ENCD) + et;
                float a8[8];
#pragma unroll
                for (int j = 0; j < 8; j++) a8[j] = 0.f;
#pragma unroll 4
                for (int r = rg; r < RR; r += 4) {
                    float4 v = ep4[(size_t)r * 256];
                    const __half2* hv = (const __half2*)&v;
                    float a = s_sc[r];
#pragma unroll
                    for (int j = 0; j < 4; j++) {
                        float2 f = __half22float2(hv[j]);
                        a8[2 * j] += a * f.x;
                        a8[2 * j + 1] += a * f.y;
                    }
                }
#pragma unroll
                for (int j = 0; j < 8; j++) s_part[rg * 2048 + et * 8 + j] = a8[j];
            }
            __syncthreads();

#pragma unroll
            for (int j = 0; j < 2; j++) {
                int e = tid * 2 + j;
                float v = (s_part[e] + s_part[2048 + e]) + (s_part[4096 + e] + s_part[6144 + e]);
                v *= inv;
                float gp = hproj[b * 4608 + 512 + e];
                ctx[b * ENCD + e] = v / (1.f + expf(-gp));
                gadd[b * 2048 + e] = embproj[((size_t)b * TSTEPS + t) * 2048 + e]
                                   + hproj[b * 4608 + 2560 + e];
            }
        }
        grid_barrier(++epoch * NB);

        // ---- phase 3: gates partials = ctx @ W_ih[:,512:]^T (32 n-tiles x 4 z) ----
        {
            int n0 = (bid & 31) * 64;
            int z = bid >> 5;
            gemm64_1024(smem_raw, ctx, ENCD, W_ih + 512, EMBD + ENCD, nullptr,
                        gpart + (size_t)z * BATCH * 2048, 2048, n0, 512, z * 512, false);
        }
        grid_barrier(++epoch * NB);

        // ---- phase 4: LSTM pointwise (block = batch row) ----
        if (tid < 512) {
            const int b = bid;
            const int d = tid;
            float gt[4];
#pragma unroll
            for (int q = 0; q < 4; q++) {
                int j = b * 2048 + q * 512 + d;
                float s = gadd[j];
#pragma unroll
                for (int z = 0; z < 4; z++) s += gpart[(size_t)z * BATCH * 2048 + j];
                gt[q] = s;
            }
            float i_ = 1.f / (1.f + expf(-gt[0]));
            float f_ = 1.f / (1.f + expf(-gt[1]));
            float g_ = tanhf(gt[2]);
            float o_ = 1.f / (1.f + expf(-gt[3]));
            float c = state[b * 1024 + 512 + d];
            float cn = f_ * c + i_ * g_;
            float hn = o_ * tanhf(cn);
            state[b * 1024 + d] = hn;
            state[b * 1024 + 512 + d] = cn;
            Hh[((size_t)b * TSTEPS + t) * DECD + d] = __float2half_rn(hn);
        }
        grid_barrier(++epoch * NB);
    }
}

// ---------------- small kernels ----------------
__global__ void bsum_kernel(float* __restrict__ out, const float* __restrict__ a,
                            const float* __restrict__ b) {
    int i = blockIdx.x * blockDim.x + threadIdx.x;
    if (i < 2048) out[i] = a[i] + b[i];
}

__global__ void gather_kernel(const int* __restrict__ cap, const float* __restrict__ table,
                              float* __restrict__ E) {
    int bt = blockIdx.x;
    int b = bt / TSTEPS, tt = bt % TSTEPS;
    int idx = cap[b * (TSTEPS + 1) + tt];
    const float4* src = (const float4*)(table + (size_t)idx * EMBD);
    float4* dst = (float4*)(E + (size_t)bt * EMBD);
    dst[threadIdx.x] = src[threadIdx.x];
}

__global__ void prep_enc_kernel(const float* __restrict__ enc, __half* __restrict__ ench,
                                float* __restrict__ mean) {
    int b = blockIdx.y;
    int e = blockIdx.x * 256 + threadIdx.x;
    const float* ep = enc + (size_t)b * RR * ENCD + e;
    __half* op = ench + (size_t)b * RR * ENCD + e;
    float acc = 0.f;
#pragma unroll 4
    for (int r = 0; r < RR; r++) {
        float v = ep[(size_t)r * ENCD];
        acc += v;
        op[(size_t)r * ENCD] = __float2half_rn(v);
    }
    mean[b * ENCD + e] = acc * (1.f / (float)RR);
}

// ---------------- host ----------------
static float* symaddr(const void* sym) {
    void* p = nullptr;
    cudaGetSymbolAddress(&p, sym);
    return (float*)p;
}

template <int BN, typename AT, typename OutT>
static void launch_g(const AT* A, int lda, const float* B, int ldb,
                     const float* bias, const float* Csrc, int ldsrc,
                     OutT* C, int ldc, size_t zstride,
                     int M, int N, int K, int zsplit) {
    dim3 grid((N + BN - 1) / BN, M / 128, zsplit);
    int smem = 2 * stage_b(BN, (int)sizeof(AT));
    gemm_f16<BN, AT, OutT><<<grid, 256, smem>>>(A, lda, B, ldb, bias, Csrc, ldsrc, C, ldc,
                                                zstride, N, K / zsplit);
}

extern "C" void kernel_launch(void* const* d_in, const int* in_sizes, int n_in,
                              void* d_out, int out_size) {
    const float* enc       = (const float*)d_in[0];
    const int*   captions  = (const int*)d_in[1];
    const float* W_enc_att = (const float*)d_in[2];
    const float* b_enc_att = (const float*)d_in[3];
    const float* W_dec_att = (const float*)d_in[4];
    const float* b_dec_att = (const float*)d_in[5];
    const float* W_full    = (const float*)d_in[6];
    const float* b_full    = (const float*)d_in[7];
    const float* emb_table = (const float*)d_in[8];
    const float* W_ih      = (const float*)d_in[9];
    const float* W_hh      = (const float*)d_in[10];
    const float* b_ih      = (const float*)d_in[11];
    const float* b_hh      = (const float*)d_in[12];
    const float* W_init_h  = (const float*)d_in[13];
    const float* b_init_h  = (const float*)d_in[14];
    const float* W_init_c  = (const float*)d_in[15];
    const float* b_init_c  = (const float*)d_in[16];
    const float* W_fbeta   = (const float*)d_in[17];
    const float* b_fbeta   = (const float*)d_in[18];
    const float* W_fc      = (const float*)d_in[19];
    const float* b_fc      = (const float*)d_in[20];

    float* out_pred  = (float*)d_out;
    float* out_alpha = out_pred + (size_t)BATCH * TSTEPS * VOC;

    __half* att1h = (__half*)symaddr(g_att1h);
    __half* ench  = (__half*)symaddr(g_ench);
    __half* Hh    = (__half*)symaddr(g_Hh);
    float* meanb  = symaddr(g_mean);
    float* state  = symaddr(g_state);
    float* hproj  = symaddr(g_hproj);
    float* ctx    = symaddr(g_ctx);
    float* gadd   = symaddr(g_gadd);
    float* gpart  = symaddr(g_gpart);
    float* E      = symaddr(g_E);
    float* embprj = symaddr(g_embproj);
    float* Wcat   = symaddr(g_Wcat);
    float* bcat   = symaddr(g_bcat);
    float* bsum   = symaddr(g_bsum);
    float* Winit  = symaddr(g_Winit);
    float* binit  = symaddr(g_binit);
    void* barsp = nullptr;
    cudaGetSymbolAddress(&barsp, g_bars);

    const int SM64F = 2 * stage_b(64, 4);
    const int SM128F = 2 * stage_b(128, 4);
    const int SM128H = 2 * stage_b(128, 2);
    cudaFuncSetAttribute((const void*)gemm_f16<64, float, float>,
                         cudaFuncAttributeMaxDynamicSharedMemorySize, SM64F);
    cudaFuncSetAttribute((const void*)gemm_f16<128, float, float>,
                         cudaFuncAttributeMaxDynamicSharedMemorySize, SM128F);
    cudaFuncSetAttribute((const void*)gemm_f16<128, __half, __half>,
                         cudaFuncAttributeMaxDynamicSharedMemorySize, SM128H);
    cudaFuncSetAttribute((const void*)gemm_f16<128, __half, float>,
                         cudaFuncAttributeMaxDynamicSharedMemorySize, SM128H);
    cudaFuncSetAttribute((const void*)loop_kernel,
                         cudaFuncAttributeMaxDynamicSharedMemorySize, SM64F);

    // ---- prologue: weight concats ----
    cudaMemcpyAsync(Wcat, W_dec_att, (size_t)512 * 512 * 4, cudaMemcpyDeviceToDevice, 0);
    cudaMemcpyAsync(Wcat + 512 * 512, W_fbeta, (size_t)2048 * 512 * 4, cudaMemcpyDeviceToDevice, 0);
    cudaMemcpyAsync(Wcat + 2560 * 512, W_hh, (size_t)2048 * 512 * 4, cudaMemcpyDeviceToDevice, 0);
    cudaMemcpyAsync(bcat, b_dec_att, 512 * 4, cudaMemcpyDeviceToDevice, 0);
    cudaMemcpyAsync(bcat + 512, b_fbeta, 2048 * 4, cudaMemcpyDeviceToDevice, 0);
    cudaMemsetAsync(bcat + 2560, 0, 2048 * 4, 0);
    cudaMemcpyAsync(Winit, W_init_h, (size_t)512 * 2048 * 4, cudaMemcpyDeviceToDevice, 0);
    cudaMemcpyAsync(Winit + (size_t)512 * 2048, W_init_c, (size_t)512 * 2048 * 4,
                    cudaMemcpyDeviceToDevice, 0);
    cudaMemcpyAsync(binit, b_init_h, 512 * 4, cudaMemcpyDeviceToDevice, 0);
    cudaMemcpyAsync(binit + 512, b_init_c, 512 * 4, cudaMemcpyDeviceToDevice, 0);
    cudaMemsetAsync(barsp, 0, 8 * 32 * 4, 0);

    bsum_kernel<<<8, 256>>>(bsum, b_ih, b_hh);
    prep_enc_kernel<<<dim3(8, BATCH), 256>>>(enc, ench, meanb);
    // state = mean @ [W_init_h; W_init_c]^T + [b_init_h; b_init_c]
    launch_g<64, float, float>(meanb, ENCD, Winit, ENCD, binit, nullptr, 0, state, 1024, 0,
                               BATCH, 1024, ENCD, 1);
    gather_kernel<<<BATCH * TSTEPS, 128>>>(captions, emb_table, E);
    // embproj (all t): E @ W_ih[:, :512]^T + (b_ih + b_hh)
    launch_g<128, float, float>(E, EMBD, W_ih, EMBD + ENCD, bsum, nullptr, 0, embprj, 2048, 0,
                                BATCH * TSTEPS, 2048, EMBD, 1);
    // att1 = ench(fp16) @ W_enc_att^T + b_enc_att (fp16 output) — halved A traffic
    launch_g<128, __half, __half>(ench, ENCD, W_enc_att, ENCD, b_enc_att, nullptr, 0,
                                  att1h, ATTD, 0, BATCH * RR, ATTD, ENCD, 1);

    // ---- recurrence: ONE persistent kernel (1024 threads/block) ----
    loop_kernel<<<NB, 1024, SM64F>>>(att1h, ench, state, hproj, Wcat, bcat,
                                     W_full, b_full, embprj, ctx, gadd, gpart,
                                     W_ih, Hh, out_alpha);

    // ---- batched fc from fp16 H: preds = H @ W_fc^T + b_fc ----
    launch_g<128, __half, float>(Hh, DECD, W_fc, DECD, b_fc, nullptr, 0, out_pred, VOC, 0,
                                 BATCH * TSTEPS, VOC, DECD, 1);
}

// round 14
// speedup vs baseline: 1.2284x; 1.2179x over previous
#include <cuda_runtime.h>
#include <cuda_fp16.h>
#include <cstdint>
#include <cstddef>

#define BATCH 128
#define RR    196
#define ENCD  2048
#define ATTD  512
#define DECD  512
#define EMBD  512
#define VOC   10000
#define TSTEPS 20

#define SROW 36      // float smem row stride (floats)
#define HROW 40      // half smem row stride (halves)

// ---------------- device scratch (static allocation only) ----------------
__device__ __half g_att1h[(size_t)BATCH * RR * ATTD];
__device__ __half g_ench[(size_t)BATCH * RR * ENCD];
__device__ float g_mean[BATCH * ENCD];
__device__ float g_state[BATCH * 1024];            // [h | c]
__device__ float g_hproj[BATCH * 4608];            // [att2 | fbeta_pre | hWhh]
__device__ __half g_ctxh[BATCH * ENCD];            // fp16 ctx (gates GEMM A operand)
__device__ float g_gadd[BATCH * 2048];
__device__ float g_gpart[4 * BATCH * 2048];
__device__ __half g_Hh[(size_t)BATCH * TSTEPS * DECD];   // fp16 h_t (fc A operand)
__device__ float g_E[BATCH * TSTEPS * EMBD];
__device__ float g_embproj[BATCH * TSTEPS * 2048];
__device__ float g_Wcat[4608 * 512];
__device__ float g_bcat[4608];
__device__ float g_bsum[2048];
__device__ float g_Winit[1024 * ENCD];
__device__ float g_binit[1024];

// ---------------- helpers ----------------
#define MMA_F16(c, a, b0, b1)                                               \
    asm volatile(                                                           \
        "mma.sync.aligned.m16n8k16.row.col.f32.f16.f16.f32 "                \
        "{%0,%1,%2,%3}, {%4,%5,%6,%7}, {%8,%9}, {%0,%1,%2,%3};"             \
        : "+f"(c[0]), "+f"(c[1]), "+f"(c[2]), "+f"(c[3])                    \
        : "r"(a[0]), "r"(a[1]), "r"(a[2]), "r"(a[3]), "r"(b0), "r"(b1))

__device__ __forceinline__ void cp_async16(uint32_t saddr, const void* gptr) {
    asm volatile("cp.async.cg.shared.global [%0], [%1], 16;\n" :: "r"(saddr), "l"(gptr));
}
__device__ __forceinline__ void cp_commit() { asm volatile("cp.async.commit_group;\n"); }

__device__ __forceinline__ unsigned pack_h2(float2 p) {
    __half2 h = __float22half2_rn(p);
    return *(unsigned*)&h;
}

static constexpr int stage_b(int BN, int asz) {
    return 128 * ((asz == 2) ? HROW : SROW) * asz + BN * SROW * 4;
}

// ================= unified fp16 GEMM (A: f32 or f16; BM=128; BN=64/128) =================
template <int BN, typename AT, typename OutT>
__global__ void __launch_bounds__(256) gemm_f16(
    const AT* __restrict__ A, int lda,
    const float* __restrict__ Bm, int ldb,
    const float* __restrict__ bias,
    const float* __restrict__ Csrc, int ldsrc,
    OutT* __restrict__ Cbase, int ldc, size_t zstride,
    int N, int K) {
    constexpr bool AH = (sizeof(AT) == 2);
    constexpr int ABYTES = 128 * (AH ? HROW : SROW) * (int)sizeof(AT);
    constexpr int STB = ABYTES + BN * SROW * 4;
    constexpr int NI = BN / 16;
    extern __shared__ char smem[];
    const int tid = threadIdx.x;
    const int m0 = blockIdx.y * 128;
    const int n0 = blockIdx.x * BN;
    const int Koff = blockIdx.z * K;
    OutT* C = Cbase + (size_t)blockIdx.z * zstride;
    const bool final_z = (gridDim.z == 1);

    const int warp = tid >> 5, lane = tid & 31;
    const int g = lane >> 2, tg = lane & 3;
    const int wm = (warp >> 1) * 32;
    const int wn = (warp & 1) * (BN / 2);

    float acc[2][NI][4];
#pragma unroll
    for (int mi = 0; mi < 2; mi++)
#pragma unroll
        for (int ni = 0; ni < NI; ni++)
#pragma unroll
            for (int j = 0; j < 4; j++) acc[mi][ni][j] = 0.f;

    const int ntiles = K >> 5;

    auto load_stage = [&](int buf, int kt) {
        char* base = smem + buf * STB;
        const int kb = Koff + kt;
        if (AH) {
            __half* sA = (__half*)base;
#pragma unroll
            for (int i = 0; i < 2; i++) {
                int idx = tid + i * 256;          // 0..511
                int row = idx >> 2;
                int q = (idx & 3) * 8;
                uint32_t d = (uint32_t)__cvta_generic_to_shared(sA + row * HROW + q);
                cp_async16(d, (const __half*)A + (size_t)(m0 + row) * lda + kb + q);
            }
        } else {
            float* sA = (float*)base;
#pragma unroll
            for (int i = 0; i < 4; i++) {
                int idx = tid + i * 256;
                int row = idx >> 3;
                int q = (idx & 7) << 2;
                uint32_t d = (uint32_t)__cvta_generic_to_shared(sA + row * SROW + q);
                cp_async16(d, (const float*)A + (size_t)(m0 + row) * lda + kb + q);
            }
        }
        float* sB = (float*)(base + ABYTES);
#pragma unroll
        for (int i = 0; i < BN / 32; i++) {
            int idx = tid + i * 256;
            int row = idx >> 3;
            int q = (idx & 7) << 2;
            int nr = n0 + row;
            if (nr >= N) nr = N - 1;
            uint32_t d = (uint32_t)__cvta_generic_to_shared(sB + row * SROW + q);
            cp_async16(d, Bm + (size_t)nr * ldb + kb + q);
        }
        cp_commit();
    };

    load_stage(0, 0);

    for (int kt = 0; kt < ntiles; kt++) {
        if (kt + 1 < ntiles) {
            load_stage((kt + 1) & 1, (kt + 1) << 5);
            asm volatile("cp.async.wait_group 1;\n");
        } else {
            asm volatile("cp.async.wait_group 0;\n");
        }
        __syncthreads();

        const char* base = smem + (kt & 1) * STB;
        const float* sB = (const float*)(base + ABYTES);

#pragma unroll
        for (int ks = 0; ks < 2; ks++) {
            const int k0 = ks * 16;
            unsigned ah[2][4];
            if (AH) {
                const __half* sAh = (const __half*)base;
#pragma unroll
                for (int mi = 0; mi < 2; mi++) {
                    int r = wm + mi * 16;
                    ah[mi][0] = *(const unsigned*)&sAh[(r + g) * HROW + k0 + 2 * tg];
                    ah[mi][1] = *(const unsigned*)&sAh[(r + g + 8) * HROW + k0 + 2 * tg];
                    ah[mi][2] = *(const unsigned*)&sAh[(r + g) * HROW + k0 + 8 + 2 * tg];
                    ah[mi][3] = *(const unsigned*)&sAh[(r + g + 8) * HROW + k0 + 8 + 2 * tg];
                }
            } else {
                const float* sAf = (const float*)base;
#pragma unroll
                for (int mi = 0; mi < 2; mi++) {
                    int r = wm + mi * 16;
                    ah[mi][0] = pack_h2(*(const float2*)&sAf[(r + g) * SROW + k0 + 2 * tg]);
                    ah[mi][1] = pack_h2(*(const float2*)&sAf[(r + g + 8) * SROW + k0 + 2 * tg]);
                    ah[mi][2] = pack_h2(*(const float2*)&sAf[(r + g) * SROW + k0 + 8 + 2 * tg]);
                    ah[mi][3] = pack_h2(*(const float2*)&sAf[(r + g + 8) * SROW + k0 + 8 + 2 * tg]);
                }
            }
#pragma unroll
            for (int ni = 0; ni < NI; ni++) {
                int cb = wn + ni * 8;
                unsigned b0 = pack_h2(*(const float2*)&sB[(cb + g) * SROW + k0 + 2 * tg]);
                unsigned b1 = pack_h2(*(const float2*)&sB[(cb + g) * SROW + k0 + 8 + 2 * tg]);
#pragma unroll
                for (int mi = 0; mi < 2; mi++) MMA_F16(acc[mi][ni], ah[mi], b0, b1);
            }
        }
        __syncthreads();
    }

#pragma unroll
    for (int mi = 0; mi < 2; mi++) {
#pragma unroll
        for (int ni = 0; ni < NI; ni++) {
            int r0 = m0 + wm + mi * 16 + g;
            int c0 = n0 + wn + ni * 8 + tg * 2;
#pragma unroll
            for (int half = 0; half < 2; half++) {
                int rr = r0 + half * 8;
#pragma unroll
                for (int j = 0; j < 2; j++) {
                    int cc = c0 + j;
                    if (cc >= N) continue;
                    float v = acc[mi][ni][half * 2 + j];
                    if (final_z) {
                        if (bias) v += bias[cc];
                        if (Csrc) v += Csrc[(size_t)rr * ldsrc + cc];
                    }
                    C[(size_t)rr * ldc + cc] = (OutT)v;
                }
            }
        }
    }
}

// ---------------- small kernels ----------------
__global__ void bsum_kernel(float* __restrict__ out, const float* __restrict__ a,
                            const float* __restrict__ b) {
    int i = blockIdx.x * blockDim.x + threadIdx.x;
    if (i < 2048) out[i] = a[i] + b[i];
}

__global__ void gather_kernel(const int* __restrict__ cap, const float* __restrict__ table,
                              float* __restrict__ E) {
    int bt = blockIdx.x;
    int b = bt / TSTEPS, tt = bt % TSTEPS;
    int idx = cap[b * (TSTEPS + 1) + tt];
    const float4* src = (const float4*)(table + (size_t)idx * EMBD);
    float4* dst = (float4*)(E + (size_t)bt * EMBD);
    dst[threadIdx.x] = src[threadIdx.x];
}

__global__ void prep_enc_kernel(const float* __restrict__ enc, __half* __restrict__ ench,
                                float* __restrict__ mean) {
    int b = blockIdx.y;
    int e = blockIdx.x * 256 + threadIdx.x;
    const float* ep = enc + (size_t)b * RR * ENCD + e;
    __half* op = ench + (size_t)b * RR * ENCD + e;
    float acc = 0.f;
#pragma unroll 4
    for (int r = 0; r < RR; r++) {
        float v = ep[(size_t)r * ENCD];
        acc += v;
        op[(size_t)r * ENCD] = __float2half_rn(v);
    }
    mean[b * ENCD + e] = acc * (1.f / (float)RR);
}

// ============ fused attention + softmax + context + gadd (one block per b) ============
__global__ void __launch_bounds__(1024) att_ctx_kernel(
    const __half* __restrict__ att1h, const __half* __restrict__ ench,
    const float* __restrict__ hproj,
    const float* __restrict__ wfull, const float* __restrict__ bfull,
    const float* __restrict__ embproj,
    __half* __restrict__ ctxh, float* __restrict__ gadd,
    float* __restrict__ out_alpha, int t) {
    int b = blockIdx.x;
    int tid = threadIdx.x;  // 1024
    int warp = tid >> 5, lane = tid & 31;
    __shared__ float s_att2[512], s_wf[512], s_sc[RR], s_red[32];
    __shared__ float s_part[4][2048];
    if (tid < 512) {
        s_att2[tid] = hproj[b * 4608 + tid];
        s_wf[tid] = wfull[tid];
    }
    __syncthreads();

    // scores: warp per r, float4 (8 halves) loads
    float bf = bfull[0];
    for (int r = warp; r < RR; r += 32) {
        const float4* ap = (const float4*)(att1h + (size_t)(b * RR + r) * ATTD);
        float s = 0.f;
#pragma unroll
        for (int i = 0; i < 2; i++) {
            float4 v = ap[lane + i * 32];
            const __half2* hv = (const __half2*)&v;
            int a = (lane + i * 32) * 8;
#pragma unroll
            for (int j = 0; j < 4; j++) {
                float2 f = __half22float2(hv[j]);
                s += fmaxf(f.x + s_att2[a + 2 * j], 0.f) * s_wf[a + 2 * j]
                   + fmaxf(f.y + s_att2[a + 2 * j + 1], 0.f) * s_wf[a + 2 * j + 1];
            }
        }
#pragma unroll
        for (int o = 16; o; o >>= 1) s += __shfl_xor_sync(0xffffffffu, s, o);
        if (lane == 0) s_sc[r] = s + bf;
    }
    __syncthreads();

    // softmax
    float m = (tid < RR) ? s_sc[tid] : -1e30f;
#pragma unroll
    for (int o = 16; o; o >>= 1) m = fmaxf(m, __shfl_xor_sync(0xffffffffu, m, o));
    if (lane == 0) s_red[warp] = m;
    __syncthreads();
    m = s_red[0];
#pragma unroll
    for (int w = 1; w < 32; w++) m = fmaxf(m, s_red[w]);
    __syncthreads();
    float sum = 0.f;
    if (tid < RR) {
        float e = expf(s_sc[tid] - m);
        s_sc[tid] = e;
        sum = e;
    }
#pragma unroll
    for (int o = 16; o; o >>= 1) sum += __shfl_xor_sync(0xffffffffu, sum, o);
    if (lane == 0) s_red[warp] = sum;
    __syncthreads();
    sum = 0.f;
#pragma unroll
    for (int w = 0; w < 32; w++) sum += s_red[w];
    float inv = 1.f / sum;
    if (tid < RR) out_alpha[((size_t)b * TSTEPS + t) * RR + tid] = s_sc[tid] * inv;
    __syncthreads();

    // context: 4 row-groups x 256 e-threads, float4 (8 halves) per row
    {
        int rg = tid >> 8;
        int et = tid & 255;
        const float4* ep4 = (const float4*)(ench + (size_t)b * RR * ENCD) + et;
        float a8[8];
#pragma unroll
        for (int j = 0; j < 8; j++) a8[j] = 0.f;
#pragma unroll 4
        for (int r = rg; r < RR; r += 4) {
            float4 v = ep4[(size_t)r * 256];
            const __half2* hv = (const __half2*)&v;
            float a = s_sc[r];
#pragma unroll
            for (int j = 0; j < 4; j++) {
                float2 f = __half22float2(hv[j]);
                a8[2 * j] += a * f.x;
                a8[2 * j + 1] += a * f.y;
            }
        }
#pragma unroll
        for (int j = 0; j < 8; j++) s_part[rg][et * 8 + j] = a8[j];
    }
    __syncthreads();

    {
        int e = tid * 2;
        float v0 = (s_part[0][e] + s_part[1][e]) + (s_part[2][e] + s_part[3][e]);
        float v1 = (s_part[0][e + 1] + s_part[1][e + 1]) + (s_part[2][e + 1] + s_part[3][e + 1]);
        v0 *= inv;
        v1 *= inv;
        float g0 = hproj[b * 4608 + 512 + e];
        float g1 = hproj[b * 4608 + 512 + e + 1];
        v0 /= (1.f + expf(-g0));
        v1 /= (1.f + expf(-g1));
        *(__half2*)&ctxh[b * ENCD + e] = __floats2half2_rn(v0, v1);
        gadd[b * 2048 + e] = embproj[((size_t)b * TSTEPS + t) * 2048 + e]
                           + hproj[b * 4608 + 2560 + e];
        gadd[b * 2048 + e + 1] = embproj[((size_t)b * TSTEPS + t) * 2048 + e + 1]
                               + hproj[b * 4608 + 2560 + e + 1];
    }
}

// sums 4 split-K partials + gadd, LSTM pointwise, writes fp32 state + fp16 Hh
__global__ void lstm_kernel(const float* __restrict__ gpart, const float* __restrict__ gadd,
                            float* __restrict__ state, __half* __restrict__ Hh, int t) {
    int b = blockIdx.x, d = threadIdx.x;  // 512 threads
    float gt[4];
#pragma unroll
    for (int q = 0; q < 4; q++) {
        int j = b * 2048 + q * 512 + d;
        float s = gadd[j];
#pragma unroll
        for (int z = 0; z < 4; z++) s += gpart[z * BATCH * 2048 + j];
        gt[q] = s;
    }
    float i_ = 1.f / (1.f + expf(-gt[0]));
    float f_ = 1.f / (1.f + expf(-gt[1]));
    float g_ = tanhf(gt[2]);
    float o_ = 1.f / (1.f + expf(-gt[3]));
    float c = state[b * 1024 + 512 + d];
    float cn = f_ * c + i_ * g_;
    float hn = o_ * tanhf(cn);
    state[b * 1024 + d] = hn;
    state[b * 1024 + 512 + d] = cn;
    Hh[((size_t)b * TSTEPS + t) * DECD + d] = __float2half_rn(hn);
}

// ---------------- host ----------------
static float* symaddr(const void* sym) {
    void* p = nullptr;
    cudaGetSymbolAddress(&p, sym);
    return (float*)p;
}

template <int BN, typename AT, typename OutT>
static void launch_g(const AT* A, int lda, const float* B, int ldb,
                     const float* bias, const float* Csrc, int ldsrc,
                     OutT* C, int ldc, size_t zstride,
                     int M, int N, int K, int zsplit) {
    dim3 grid((N + BN - 1) / BN, M / 128, zsplit);
    int smem = 2 * stage_b(BN, (int)sizeof(AT));
    gemm_f16<BN, AT, OutT><<<grid, 256, smem>>>(A, lda, B, ldb, bias, Csrc, ldsrc, C, ldc,
                                                zstride, N, K / zsplit);
}

extern "C" void kernel_launch(void* const* d_in, const int* in_sizes, int n_in,
                              void* d_out, int out_size) {
    const float* enc       = (const float*)d_in[0];
    const int*   captions  = (const int*)d_in[1];
    const float* W_enc_att = (const float*)d_in[2];
    const float* b_enc_att = (const float*)d_in[3];
    const float* W_dec_att = (const float*)d_in[4];
    const float* b_dec_att = (const float*)d_in[5];
    const float* W_full    = (const float*)d_in[6];
    const float* b_full    = (const float*)d_in[7];
    const float* emb_table = (const float*)d_in[8];
    const float* W_ih      = (const float*)d_in[9];
    const float* W_hh      = (const float*)d_in[10];
    const float* b_ih      = (const float*)d_in[11];
    const float* b_hh      = (const float*)d_in[12];
    const float* W_init_h  = (const float*)d_in[13];
    const float* b_init_h  = (const float*)d_in[14];
    const float* W_init_c  = (const float*)d_in[15];
    const float* b_init_c  = (const float*)d_in[16];
    const float* W_fbeta   = (const float*)d_in[17];
    const float* b_fbeta   = (const float*)d_in[18];
    const float* W_fc      = (const float*)d_in[19];
    const float* b_fc      = (const float*)d_in[20];

    float* out_pred  = (float*)d_out;
    float* out_alpha = out_pred + (size_t)BATCH * TSTEPS * VOC;

    __half* att1h = (__half*)symaddr(g_att1h);
    __half* ench  = (__half*)symaddr(g_ench);
    __half* ctxh  = (__half*)symaddr(g_ctxh);
    __half* Hh    = (__half*)symaddr(g_Hh);
    float* meanb  = symaddr(g_mean);
    float* state  = symaddr(g_state);
    float* hproj  = symaddr(g_hproj);
    float* gadd   = symaddr(g_gadd);
    float* gpart  = symaddr(g_gpart);
    float* E      = symaddr(g_E);
    float* embprj = symaddr(g_embproj);
    float* Wcat   = symaddr(g_Wcat);
    float* bcat   = symaddr(g_bcat);
    float* bsum   = symaddr(g_bsum);
    float* Winit  = symaddr(g_Winit);
    float* binit  = symaddr(g_binit);

    const int SM64F = 2 * stage_b(64, 4);
    const int SM64H = 2 * stage_b(64, 2);
    const int SM128F = 2 * stage_b(128, 4);
    const int SM128H = 2 * stage_b(128, 2);
    cudaFuncSetAttribute((const void*)gemm_f16<64, float, float>,
                         cudaFuncAttributeMaxDynamicSharedMemorySize, SM64F);
    cudaFuncSetAttribute((const void*)gemm_f16<64, __half, float>,
                         cudaFuncAttributeMaxDynamicSharedMemorySize, SM64H);
    cudaFuncSetAttribute((const void*)gemm_f16<128, float, float>,
                         cudaFuncAttributeMaxDynamicSharedMemorySize, SM128F);
    cudaFuncSetAttribute((const void*)gemm_f16<128, __half, __half>,
                         cudaFuncAttributeMaxDynamicSharedMemorySize, SM128H);
    cudaFuncSetAttribute((const void*)gemm_f16<128, __half, float>,
                         cudaFuncAttributeMaxDynamicSharedMemorySize, SM128H);

    // ---- prologue: weight concats ----
    cudaMemcpyAsync(Wcat, W_dec_att, (size_t)512 * 512 * 4, cudaMemcpyDeviceToDevice, 0);
    cudaMemcpyAsync(Wcat + 512 * 512, W_fbeta, (size_t)2048 * 512 * 4, cudaMemcpyDeviceToDevice, 0);
    cudaMemcpyAsync(Wcat + 2560 * 512, W_hh, (size_t)2048 * 512 * 4, cudaMemcpyDeviceToDevice, 0);
    cudaMemcpyAsync(bcat, b_dec_att, 512 * 4, cudaMemcpyDeviceToDevice, 0);
    cudaMemcpyAsync(bcat + 512, b_fbeta, 2048 * 4, cudaMemcpyDeviceToDevice, 0);
    cudaMemsetAsync(bcat + 2560, 0, 2048 * 4, 0);
    cudaMemcpyAsync(Winit, W_init_h, (size_t)512 * 2048 * 4, cudaMemcpyDeviceToDevice, 0);
    cudaMemcpyAsync(Winit + (size_t)512 * 2048, W_init_c, (size_t)512 * 2048 * 4,
                    cudaMemcpyDeviceToDevice, 0);
    cudaMemcpyAsync(binit, b_init_h, 512 * 4, cudaMemcpyDeviceToDevice, 0);
    cudaMemcpyAsync(binit + 512, b_init_c, 512 * 4, cudaMemcpyDeviceToDevice, 0);

    bsum_kernel<<<8, 256>>>(bsum, b_ih, b_hh);
    prep_enc_kernel<<<dim3(8, BATCH), 256>>>(enc, ench, meanb);
    // state = mean @ [W_init_h; W_init_c]^T + [b_init_h; b_init_c]
    launch_g<64, float, float>(meanb, ENCD, Winit, ENCD, binit, nullptr, 0, state, 1024, 0,
                               BATCH, 1024, ENCD, 1);
    gather_kernel<<<BATCH * TSTEPS, 128>>>(captions, emb_table, E);
    // embproj (all t): E @ W_ih[:, :512]^T + (b_ih + b_hh)
    launch_g<128, float, float>(E, EMBD, W_ih, EMBD + ENCD, bsum, nullptr, 0, embprj, 2048, 0,
                                BATCH * TSTEPS, 2048, EMBD, 1);
    // att1 = ench(fp16) @ W_enc_att^T + b_enc_att (fp16 out) — halved A traffic
    launch_g<128, __half, __half>(ench, ENCD, W_enc_att, ENCD, b_enc_att, nullptr, 0,
                                  att1h, ATTD, 0, BATCH * RR, ATTD, ENCD, 1);

    // ---- recurrence (R11 structure: 4 graph-launched kernels per step) ----
    for (int t = 0; t < TSTEPS; t++) {
        // hproj = h @ [W_dec_att; W_fbeta; W_hh]^T + [b_dec_att; b_fbeta; 0]
        launch_g<64, float, float>(state, 1024, Wcat, 512, bcat, nullptr, 0, hproj, 4608, 0,
                                   BATCH, 4608, DECD, 1);
        att_ctx_kernel<<<BATCH, 1024>>>(att1h, ench, hproj, W_full, b_full, embprj,
                                        ctxh, gadd, out_alpha, t);
        // gates partials = ctx(fp16) @ W_ih[:, 512:]^T   (split-K = 4)
        launch_g<64, __half, float>(ctxh, ENCD, W_ih + 512, EMBD + ENCD, nullptr, nullptr, 0,
                                    gpart, 2048, (size_t)BATCH * 2048, BATCH, 2048, ENCD, 4);
        lstm_kernel<<<BATCH, 512>>>(gpart, gadd, state, Hh, t);
    }

    // ---- batched fc from fp16 H: preds = H @ W_fc^T + b_fc ----
    launch_g<128, __half, float>(Hh, DECD, W_fc, DECD, b_fc, nullptr, 0, out_pred, VOC, 0,
                                 BATCH * TSTEPS, VOC, DECD, 1);
}

// round 15
// speedup vs baseline: 1.4067x; 1.1451x over previous
#include <cuda_runtime.h>
#include <cuda_fp16.h>
#include <cstdint>
#include <cstddef>

#define BATCH 128
#define RR    196
#define ENCD  2048
#define ATTD  512
#define DECD  512
#define EMBD  512
#define VOC   10000
#define TSTEPS 20

#define SROW 36      // float smem row stride (floats)
#define HROW 40      // half smem row stride (halves)

// ---------------- device scratch (static allocation only) ----------------
__device__ __half g_att1h[(size_t)BATCH * RR * ATTD];
__device__ __half g_ench[(size_t)BATCH * RR * ENCD];
__device__ float g_mean[BATCH * ENCD];
__device__ float g_state[BATCH * 1024];            // [h | c]
__device__ float g_hproj[BATCH * 4608];            // [att2 | fbeta_pre | hWhh]
__device__ __half g_ctxh[BATCH * ENCD];
__device__ float g_gpart[4 * BATCH * 2048];
__device__ __half g_Hh[(size_t)BATCH * TSTEPS * DECD];
__device__ __half g_Eh[BATCH * TSTEPS * EMBD];
__device__ float g_embproj[BATCH * TSTEPS * 2048];
__device__ float g_Wcat[4608 * 512];
__device__ float g_bcat[4608];
__device__ float g_bsum[2048];
__device__ float g_Winit[1024 * ENCD];
__device__ float g_binit[1024];
// fp16 weight mirrors
__device__ __half g_Wcat_h[4608 * 512];
__device__ __half g_Wih_h[2048 * 2560];
__device__ __half g_Wfc_h[(size_t)VOC * 512];
__device__ __half g_Wenc_h[512 * 2048];
__device__ __half g_Winit_h[1024 * 2048];

// ---------------- helpers ----------------
#define MMA_F16(c, a, b0, b1)                                               \
    asm volatile(                                                           \
        "mma.sync.aligned.m16n8k16.row.col.f32.f16.f16.f32 "                \
        "{%0,%1,%2,%3}, {%4,%5,%6,%7}, {%8,%9}, {%0,%1,%2,%3};"             \
        : "+f"(c[0]), "+f"(c[1]), "+f"(c[2]), "+f"(c[3])                    \
        : "r"(a[0]), "r"(a[1]), "r"(a[2]), "r"(a[3]), "r"(b0), "r"(b1))

__device__ __forceinline__ void cp_async16(uint32_t saddr, const void* gptr) {
    asm volatile("cp.async.cg.shared.global [%0], [%1], 16;\n" :: "r"(saddr), "l"(gptr));
}
__device__ __forceinline__ void cp_commit() { asm volatile("cp.async.commit_group;\n"); }

__device__ __forceinline__ unsigned pack_h2(float2 p) {
    __half2 h = __float22half2_rn(p);
    return *(unsigned*)&h;
}

static constexpr int stage2(int BN, int asz, int bsz) {
    return 128 * ((asz == 2) ? HROW : SROW) * asz + BN * ((bsz == 2) ? HROW : SROW) * bsz;
}

// ========== unified GEMM: A f32/f16, B f32/f16 (fp16 MMA; BM=128; BN=64/128) ==========
template <int BN, typename AT, typename BT, typename OutT>
__global__ void __launch_bounds__(256) gemm_f16(
    const AT* __restrict__ A, int lda,
    const BT* __restrict__ Bm, int ldb,
    const float* __restrict__ bias,
    const float* __restrict__ Csrc, int ldsrc,
    OutT* __restrict__ Cbase, int ldc, size_t zstride,
    int N, int K) {
    constexpr bool AH = (sizeof(AT) == 2);
    constexpr bool BH = (sizeof(BT) == 2);
    constexpr int ABYTES = 128 * (AH ? HROW : SROW) * (int)sizeof(AT);
    constexpr int BBYTES = BN * (BH ? HROW : SROW) * (int)sizeof(BT);
    constexpr int STB = ABYTES + BBYTES;
    constexpr int NI = BN / 16;
    extern __shared__ char smem[];
    const int tid = threadIdx.x;
    const int m0 = blockIdx.y * 128;
    const int n0 = blockIdx.x * BN;
    const int Koff = blockIdx.z * K;
    OutT* C = Cbase + (size_t)blockIdx.z * zstride;
    const bool final_z = (gridDim.z == 1);

    const int warp = tid >> 5, lane = tid & 31;
    const int g = lane >> 2, tg = lane & 3;
    const int wm = (warp >> 1) * 32;
    const int wn = (warp & 1) * (BN / 2);

    float acc[2][NI][4];
#pragma unroll
    for (int mi = 0; mi < 2; mi++)
#pragma unroll
        for (int ni = 0; ni < NI; ni++)
#pragma unroll
            for (int j = 0; j < 4; j++) acc[mi][ni][j] = 0.f;

    const int ntiles = K >> 5;

    auto load_stage = [&](int buf, int kt) {
        char* base = smem + buf * STB;
        const int kb = Koff + kt;
        if (AH) {
            __half* sA = (__half*)base;
#pragma unroll
            for (int i = 0; i < 2; i++) {
                int idx = tid + i * 256;
                int row = idx >> 2;
                int q = (idx & 3) * 8;
                uint32_t d = (uint32_t)__cvta_generic_to_shared(sA + row * HROW + q);
                cp_async16(d, (const __half*)A + (size_t)(m0 + row) * lda + kb + q);
            }
        } else {
            float* sA = (float*)base;
#pragma unroll
            for (int i = 0; i < 4; i++) {
                int idx = tid + i * 256;
                int row = idx >> 3;
                int q = (idx & 7) << 2;
                uint32_t d = (uint32_t)__cvta_generic_to_shared(sA + row * SROW + q);
                cp_async16(d, (const float*)A + (size_t)(m0 + row) * lda + kb + q);
            }
        }
        if (BH) {
            __half* sB = (__half*)(base + ABYTES);
#pragma unroll
            for (int i = 0; i < BN / 64; i++) {
                int idx = tid + i * 256;
                int row = idx >> 2;
                int q = (idx & 3) * 8;
                int nr = n0 + row;
                if (nr >= N) nr = N - 1;
                uint32_t d = (uint32_t)__cvta_generic_to_shared(sB + row * HROW + q);
                cp_async16(d, (const __half*)Bm + (size_t)nr * ldb + kb + q);
            }
        } else {
            float* sB = (float*)(base + ABYTES);
#pragma unroll
            for (int i = 0; i < BN / 32; i++) {
                int idx = tid + i * 256;
                int row = idx >> 3;
                int q = (idx & 7) << 2;
                int nr = n0 + row;
                if (nr >= N) nr = N - 1;
                uint32_t d = (uint32_t)__cvta_generic_to_shared(sB + row * SROW + q);
                cp_async16(d, (const float*)Bm + (size_t)nr * ldb + kb + q);
            }
        }
        cp_commit();
    };

    load_stage(0, 0);

    for (int kt = 0; kt < ntiles; kt++) {
        if (kt + 1 < ntiles) {
            load_stage((kt + 1) & 1, (kt + 1) << 5);
            asm volatile("cp.async.wait_group 1;\n");
        } else {
            asm volatile("cp.async.wait_group 0;\n");
        }
        __syncthreads();

        const char* base = smem + (kt & 1) * STB;

#pragma unroll
        for (int ks = 0; ks < 2; ks++) {
            const int k0 = ks * 16;
            unsigned ah[2][4];
            if (AH) {
                const __half* sAh = (const __half*)base;
#pragma unroll
                for (int mi = 0; mi < 2; mi++) {
                    int r = wm + mi * 16;
                    ah[mi][0] = *(const unsigned*)&sAh[(r + g) * HROW + k0 + 2 * tg];
                    ah[mi][1] = *(const unsigned*)&sAh[(r + g + 8) * HROW + k0 + 2 * tg];
                    ah[mi][2] = *(const unsigned*)&sAh[(r + g) * HROW + k0 + 8 + 2 * tg];
                    ah[mi][3] = *(const unsigned*)&sAh[(r + g + 8) * HROW + k0 + 8 + 2 * tg];
                }
            } else {
                const float* sAf = (const float*)base;
#pragma unroll
                for (int mi = 0; mi < 2; mi++) {
                    int r = wm + mi * 16;
                    ah[mi][0] = pack_h2(*(const float2*)&sAf[(r + g) * SROW + k0 + 2 * tg]);
                    ah[mi][1] = pack_h2(*(const float2*)&sAf[(r + g + 8) * SROW + k0 + 2 * tg]);
                    ah[mi][2] = pack_h2(*(const float2*)&sAf[(r + g) * SROW + k0 + 8 + 2 * tg]);
                    ah[mi][3] = pack_h2(*(const float2*)&sAf[(r + g + 8) * SROW + k0 + 8 + 2 * tg]);
                }
            }
#pragma unroll
            for (int ni = 0; ni < NI; ni++) {
                int cb = wn + ni * 8;
                unsigned b0, b1;
                if (BH) {
                    const __half* sBh = (const __half*)(base + ABYTES);
                    b0 = *(const unsigned*)&sBh[(cb + g) * HROW + k0 + 2 * tg];
                    b1 = *(const unsigned*)&sBh[(cb + g) * HROW + k0 + 8 + 2 * tg];
                } else {
                    const float* sBf = (const float*)(base + ABYTES);
                    b0 = pack_h2(*(const float2*)&sBf[(cb + g) * SROW + k0 + 2 * tg]);
                    b1 = pack_h2(*(const float2*)&sBf[(cb + g) * SROW + k0 + 8 + 2 * tg]);
                }
#pragma unroll
                for (int mi = 0; mi < 2; mi++) MMA_F16(acc[mi][ni], ah[mi], b0, b1);
            }
        }
        __syncthreads();
    }

#pragma unroll
    for (int mi = 0; mi < 2; mi++) {
#pragma unroll
        for (int ni = 0; ni < NI; ni++) {
            int r0 = m0 + wm + mi * 16 + g;
            int c0 = n0 + wn + ni * 8 + tg * 2;
#pragma unroll
            for (int half = 0; half < 2; half++) {
                int rr = r0 + half * 8;
#pragma unroll
                for (int j = 0; j < 2; j++) {
                    int cc = c0 + j;
                    if (cc >= N) continue;
                    float v = acc[mi][ni][half * 2 + j];
                    if (final_z) {
                        if (bias) v += bias[cc];
                        if (Csrc) v += Csrc[(size_t)rr * ldsrc + cc];
                    }
                    C[(size_t)rr * ldc + cc] = (OutT)v;
                }
            }
        }
    }
}

// ---------------- small kernels ----------------
__global__ void bsum_kernel(float* __restrict__ out, const float* __restrict__ a,
                            const float* __restrict__ b) {
    int i = blockIdx.x * blockDim.x + threadIdx.x;
    if (i < 2048) out[i] = a[i] + b[i];
}

// generic f32 -> f16 convert (n divisible by 4)
__global__ void f2h_kernel(const float* __restrict__ in, __half* __restrict__ out, int n) {
    int i = (blockIdx.x * blockDim.x + threadIdx.x) * 4;
    if (i >= n) return;
    float4 v = *(const float4*)(in + i);
    __half2 h0 = __float22half2_rn(make_float2(v.x, v.y));
    __half2 h1 = __float22half2_rn(make_float2(v.z, v.w));
    uint2 p;
    p.x = *(unsigned*)&h0;
    p.y = *(unsigned*)&h1;
    *(uint2*)(out + i) = p;
}

__global__ void gather_kernel(const int* __restrict__ cap, const float* __restrict__ table,
                              __half* __restrict__ E) {
    int bt = blockIdx.x;
    int b = bt / TSTEPS, tt = bt % TSTEPS;
    int idx = cap[b * (TSTEPS + 1) + tt];
    float4 v = ((const float4*)(table + (size_t)idx * EMBD))[threadIdx.x];
    __half2 h0 = __float22half2_rn(make_float2(v.x, v.y));
    __half2 h1 = __float22half2_rn(make_float2(v.z, v.w));
    uint2 p;
    p.x = *(unsigned*)&h0;
    p.y = *(unsigned*)&h1;
    *(uint2*)(E + (size_t)bt * EMBD + threadIdx.x * 4) = p;
}

__global__ void prep_enc_kernel(const float* __restrict__ enc, __half* __restrict__ ench,
                                float* __restrict__ mean) {
    int b = blockIdx.y;
    int e = blockIdx.x * 256 + threadIdx.x;
    const float* ep = enc + (size_t)b * RR * ENCD + e;
    __half* op = ench + (size_t)b * RR * ENCD + e;
    float acc = 0.f;
#pragma unroll 4
    for (int r = 0; r < RR; r++) {
        float v = ep[(size_t)r * ENCD];
        acc += v;
        op[(size_t)r * ENCD] = __float2half_rn(v);
    }
    mean[b * ENCD + e] = acc * (1.f / (float)RR);
}

// ============ fused attention + softmax + context (one block per b) ============
__global__ void __launch_bounds__(1024) att_ctx_kernel(
    const __half* __restrict__ att1h, const __half* __restrict__ ench,
    const float* __restrict__ hproj,
    const float* __restrict__ wfull, const float* __restrict__ bfull,
    __half* __restrict__ ctxh, float* __restrict__ out_alpha, int t) {
    int b = blockIdx.x;
    int tid = threadIdx.x;  // 1024
    int warp = tid >> 5, lane = tid & 31;
    __shared__ float s_att2[512], s_wf[512], s_sc[RR], s_red[32];
    __shared__ float s_part[4][2048];
    if (tid < 512) {
        s_att2[tid] = hproj[b * 4608 + tid];
        s_wf[tid] = wfull[tid];
    }
    __syncthreads();

    float bf = bfull[0];
    for (int r = warp; r < RR; r += 32) {
        const float4* ap = (const float4*)(att1h + (size_t)(b * RR + r) * ATTD);
        float s = 0.f;
#pragma unroll
        for (int i = 0; i < 2; i++) {
            float4 v = ap[lane + i * 32];
            const __half2* hv = (const __half2*)&v;
            int a = (lane + i * 32) * 8;
#pragma unroll
            for (int j = 0; j < 4; j++) {
                float2 f = __half22float2(hv[j]);
                s += fmaxf(f.x + s_att2[a + 2 * j], 0.f) * s_wf[a + 2 * j]
                   + fmaxf(f.y + s_att2[a + 2 * j + 1], 0.f) * s_wf[a + 2 * j + 1];
            }
        }
#pragma unroll
        for (int o = 16; o; o >>= 1) s += __shfl_xor_sync(0xffffffffu, s, o);
        if (lane == 0) s_sc[r] = s + bf;
    }
    __syncthreads();

    float m = (tid < RR) ? s_sc[tid] : -1e30f;
#pragma unroll
    for (int o = 16; o; o >>= 1) m = fmaxf(m, __shfl_xor_sync(0xffffffffu, m, o));
    if (lane == 0) s_red[warp] = m;
    __syncthreads();
    m = s_red[0];
#pragma unroll
    for (int w = 1; w < 32; w++) m = fmaxf(m, s_red[w]);
    __syncthreads();
    float sum = 0.f;
    if (tid < RR) {
        float e = expf(s_sc[tid] - m);
        s_sc[tid] = e;
        sum = e;
    }
#pragma unroll
    for (int o = 16; o; o >>= 1) sum += __shfl_xor_sync(0xffffffffu, sum, o);
    if (lane == 0) s_red[warp] = sum;
    __syncthreads();
    sum = 0.f;
#pragma unroll
    for (int w = 0; w < 32; w++) sum += s_red[w];
    float inv = 1.f / sum;
    if (tid < RR) out_alpha[((size_t)b * TSTEPS + t) * RR + tid] = s_sc[tid] * inv;
    __syncthreads();

    // context: 4 row-groups x 256 e-threads
    {
        int rg = tid >> 8;
        int et = tid & 255;
        const float4* ep4 = (const float4*)(ench + (size_t)b * RR * ENCD) + et;
        float a8[8];
#pragma unroll
        for (int j = 0; j < 8; j++) a8[j] = 0.f;
#pragma unroll 4
        for (int r = rg; r < RR; r += 4) {
            float4 v = ep4[(size_t)r * 256];
            const __half2* hv = (const __half2*)&v;
            float a = s_sc[r];
#pragma unroll
            for (int j = 0; j < 4; j++) {
                float2 f = __half22float2(hv[j]);
                a8[2 * j] += a * f.x;
                a8[2 * j + 1] += a * f.y;
            }
        }
#pragma unroll
        for (int j = 0; j < 8; j++) s_part[rg][et * 8 + j] = a8[j];
    }
    __syncthreads();

    {
        int e = tid * 2;
        float v0 = (s_part[0][e] + s_part[1][e]) + (s_part[2][e] + s_part[3][e]);
        float v1 = (s_part[0][e + 1] + s_part[1][e + 1]) + (s_part[2][e + 1] + s_part[3][e + 1]);
        v0 *= inv;
        v1 *= inv;
        float g0 = hproj[b * 4608 + 512 + e];
        float g1 = hproj[b * 4608 + 512 + e + 1];
        v0 /= (1.f + expf(-g0));
        v1 /= (1.f + expf(-g1));
        *(__half2*)&ctxh[b * ENCD + e] = __floats2half2_rn(v0, v1);
    }
}

// split-K reduce + (embproj + hWhh) + LSTM pointwise; writes fp32 state + fp16 Hh
__global__ void lstm_kernel(const float* __restrict__ gpart, const float* __restrict__ embproj,
                            const float* __restrict__ hproj,
                            float* __restrict__ state, __half* __restrict__ Hh, int t) {
    int b = blockIdx.x, d = threadIdx.x;  // 512 threads
    float gt[4];
#pragma unroll
    for (int q = 0; q < 4; q++) {
        int j = b * 2048 + q * 512 + d;
        float s = embproj[((size_t)b * TSTEPS + t) * 2048 + q * 512 + d]
                + hproj[b * 4608 + 2560 + q * 512 + d];
#pragma unroll
        for (int z = 0; z < 4; z++) s += gpart[z * BATCH * 2048 + j];
        gt[q] = s;
    }
    float i_ = 1.f / (1.f + expf(-gt[0]));
    float f_ = 1.f / (1.f + expf(-gt[1]));
    float g_ = tanhf(gt[2]);
    float o_ = 1.f / (1.f + expf(-gt[3]));
    float c = state[b * 1024 + 512 + d];
    float cn = f_ * c + i_ * g_;
    float hn = o_ * tanhf(cn);
    state[b * 1024 + d] = hn;
    state[b * 1024 + 512 + d] = cn;
    Hh[((size_t)b * TSTEPS + t) * DECD + d] = __float2half_rn(hn);
}

// ---------------- host ----------------
static float* symaddr(const void* sym) {
    void* p = nullptr;
    cudaGetSymbolAddress(&p, sym);
    return (float*)p;
}

template <int BN, typename AT, typename BT, typename OutT>
static void launch_g(const AT* A, int lda, const BT* B, int ldb,
                     const float* bias, const float* Csrc, int ldsrc,
                     OutT* C, int ldc, size_t zstride,
                     int M, int N, int K, int zsplit) {
    dim3 grid((N + BN - 1) / BN, M / 128, zsplit);
    int smem = 2 * stage2(BN, (int)sizeof(AT), (int)sizeof(BT));
    cudaFuncSetAttribute((const void*)gemm_f16<BN, AT, BT, OutT>,
                         cudaFuncAttributeMaxDynamicSharedMemorySize, smem);
    gemm_f16<BN, AT, BT, OutT><<<grid, 256, smem>>>(A, lda, B, ldb, bias, Csrc, ldsrc, C, ldc,
                                                    zstride, N, K / zsplit);
}

static void f2h(const float* in, __half* out, size_t n) {
    f2h_kernel<<<(unsigned)((n / 4 + 255) / 256), 256>>>(in, out, (int)n);
}

extern "C" void kernel_launch(void* const* d_in, const int* in_sizes, int n_in,
                              void* d_out, int out_size) {
    const float* enc       = (const float*)d_in[0];
    const int*   captions  = (const int*)d_in[1];
    const float* W_enc_att = (const float*)d_in[2];
    const float* b_enc_att = (const float*)d_in[3];
    const float* W_dec_att = (const float*)d_in[4];
    const float* b_dec_att = (const float*)d_in[5];
    const float* W_full    = (const float*)d_in[6];
    const float* b_full    = (const float*)d_in[7];
    const float* emb_table = (const float*)d_in[8];
    const float* W_ih      = (const float*)d_in[9];
    const float* W_hh      = (const float*)d_in[10];
    const float* b_ih      = (const float*)d_in[11];
    const float* b_hh      = (const float*)d_in[12];
    const float* W_init_h  = (const float*)d_in[13];
    const float* b_init_h  = (const float*)d_in[14];
    const float* W_init_c  = (const float*)d_in[15];
    const float* b_init_c  = (const float*)d_in[16];
    const float* W_fbeta   = (const float*)d_in[17];
    const float* b_fbeta   = (const float*)d_in[18];
    const float* W_fc      = (const float*)d_in[19];
    const float* b_fc      = (const float*)d_in[20];

    float* out_pred  = (float*)d_out;
    float* out_alpha = out_pred + (size_t)BATCH * TSTEPS * VOC;

    __half* att1h = (__half*)symaddr(g_att1h);
    __half* ench  = (__half*)symaddr(g_ench);
    __half* ctxh  = (__half*)symaddr(g_ctxh);
    __half* Hh    = (__half*)symaddr(g_Hh);
    __half* Eh    = (__half*)symaddr(g_Eh);
    float* meanb  = symaddr(g_mean);
    float* state  = symaddr(g_state);
    float* hproj  = symaddr(g_hproj);
    float* gpart  = symaddr(g_gpart);
    float* embprj = symaddr(g_embproj);
    float* Wcat   = symaddr(g_Wcat);
    float* bcat   = symaddr(g_bcat);
    float* bsum   = symaddr(g_bsum);
    float* Winit  = symaddr(g_Winit);
    float* binit  = symaddr(g_binit);
    __half* Wcat_h  = (__half*)symaddr(g_Wcat_h);
    __half* Wih_h   = (__half*)symaddr(g_Wih_h);
    __half* Wfc_h   = (__half*)symaddr(g_Wfc_h);
    __half* Wenc_h  = (__half*)symaddr(g_Wenc_h);
    __half* Winit_h = (__half*)symaddr(g_Winit_h);

    // ---- prologue: weight concats ----
    cudaMemcpyAsync(Wcat, W_dec_att, (size_t)512 * 512 * 4, cudaMemcpyDeviceToDevice, 0);
    cudaMemcpyAsync(Wcat + 512 * 512, W_fbeta, (size_t)2048 * 512 * 4, cudaMemcpyDeviceToDevice, 0);
    cudaMemcpyAsync(Wcat + 2560 * 512, W_hh, (size_t)2048 * 512 * 4, cudaMemcpyDeviceToDevice, 0);
    cudaMemcpyAsync(bcat, b_dec_att, 512 * 4, cudaMemcpyDeviceToDevice, 0);
    cudaMemcpyAsync(bcat + 512, b_fbeta, 2048 * 4, cudaMemcpyDeviceToDevice, 0);
    cudaMemsetAsync(bcat + 2560, 0, 2048 * 4, 0);
    cudaMemcpyAsync(Winit, W_init_h, (size_t)512 * 2048 * 4, cudaMemcpyDeviceToDevice, 0);
    cudaMemcpyAsync(Winit + (size_t)512 * 2048, W_init_c, (size_t)512 * 2048 * 4,
                    cudaMemcpyDeviceToDevice, 0);
    cudaMemcpyAsync(binit, b_init_h, 512 * 4, cudaMemcpyDeviceToDevice, 0);
    cudaMemcpyAsync(binit + 512, b_init_c, 512 * 4, cudaMemcpyDeviceToDevice, 0);

    // ---- fp16 weight mirrors (one-time, ~15 us) ----
    f2h(Wcat, Wcat_h, (size_t)4608 * 512);
    f2h(W_ih, Wih_h, (size_t)2048 * 2560);
    f2h(W_fc, Wfc_h, (size_t)VOC * 512);
    f2h(W_enc_att, Wenc_h, (size_t)512 * 2048);
    f2h(Winit, Winit_h, (size_t)1024 * 2048);

    bsum_kernel<<<8, 256>>>(bsum, b_ih, b_hh);
    prep_enc_kernel<<<dim3(8, BATCH), 256>>>(enc, ench, meanb);
    // state = mean @ [W_init_h; W_init_c]^T + [b_init_h; b_init_c]
    launch_g<64, float, __half, float>(meanb, ENCD, Winit_h, ENCD, binit, nullptr, 0,
                                       state, 1024, 0, BATCH, 1024, ENCD, 1);
    gather_kernel<<<BATCH * TSTEPS, 128>>>(captions, emb_table, Eh);
    // embproj (all t): Eh @ W_ih[:, :512]^T + (b_ih + b_hh)
    launch_g<128, __half, __half, float>(Eh, EMBD, Wih_h, EMBD + ENCD, bsum, nullptr, 0,
                                         embprj, 2048, 0, BATCH * TSTEPS, 2048, EMBD, 1);
    // att1 = ench @ W_enc_att^T + b_enc_att (fp16 out)
    launch_g<128, __half, __half, __half>(ench, ENCD, Wenc_h, ENCD, b_enc_att, nullptr, 0,
                                          att1h, ATTD, 0, BATCH * RR, ATTD, ENCD, 1);

    // ---- recurrence ----
    for (int t = 0; t < TSTEPS; t++) {
        // hproj = h @ [W_dec_att; W_fbeta; W_hh]^T + [b_dec_att; b_fbeta; 0]
        launch_g<64, float, __half, float>(state, 1024, Wcat_h, 512, bcat, nullptr, 0,
                                           hproj, 4608, 0, BATCH, 4608, DECD, 1);
        att_ctx_kernel<<<BATCH, 1024>>>(att1h, ench, hproj, W_full, b_full,
                                        ctxh, out_alpha, t);
        // gates partials = ctxh @ W_ih[:, 512:]^T   (split-K = 4)
        launch_g<64, __half, __half, float>(ctxh, ENCD, Wih_h + 512, EMBD + ENCD, nullptr,
                                            nullptr, 0, gpart, 2048, (size_t)BATCH * 2048,
                                            BATCH, 2048, ENCD, 4);
        lstm_kernel<<<BATCH, 512>>>(gpart, embprj, hproj, state, Hh, t);
    }

    // ---- batched fc: preds = Hh @ W_fc^T + b_fc ----
    launch_g<128, __half, __half, float>(Hh, DECD, Wfc_h, DECD, b_fc, nullptr, 0,
                                         out_pred, VOC, 0, BATCH * TSTEPS, VOC, DECD, 1);
}

// round 16
// speedup vs baseline: 1.4277x; 1.0149x over previous
#include <cuda_runtime.h>
#include <cuda_fp16.h>
#include <cstdint>
#include <cstddef>

#define BATCH 128
#define RR    196
#define ENCD  2048
#define ATTD  512
#define DECD  512
#define EMBD  512
#define VOC   10000
#define TSTEPS 20

#define SROW 36      // float smem row stride (floats)
#define HROW 40      // half smem row stride (halves)

// ---------------- device scratch (static allocation only) ----------------
__device__ __half g_att1h[(size_t)BATCH * RR * ATTD];
__device__ __half g_ench[(size_t)BATCH * RR * ENCD];
__device__ float g_mean[BATCH * ENCD];
__device__ float g_state[BATCH * 1024];            // [h | c]
__device__ float g_hproj[BATCH * 4608];            // [att2 | fbeta_pre | hWhh]
__device__ __half g_ctxh[BATCH * ENCD];
__device__ float g_gpart[4 * BATCH * 2048];
__device__ __half g_Hh[(size_t)BATCH * TSTEPS * DECD];
__device__ __half g_Eh[BATCH * TSTEPS * EMBD];
__device__ float g_embproj[BATCH * TSTEPS * 2048];
__device__ float g_Wcat[4608 * 512];
__device__ float g_bcat[4608];
__device__ float g_bsum[2048];
__device__ float g_Winit[1024 * ENCD];
__device__ float g_binit[1024];
// fp16 weight mirrors
__device__ __half g_Wcat_h[4608 * 512];
__device__ __half g_Wih_h[2048 * 2560];
__device__ __half g_Wfc_h[(size_t)VOC * 512];
__device__ __half g_Wenc_h[512 * 2048];
__device__ __half g_Winit_h[1024 * 2048];

// ---------------- helpers ----------------
#define MMA_F16(c, a, b0, b1)                                               \
    asm volatile(                                                           \
        "mma.sync.aligned.m16n8k16.row.col.f32.f16.f16.f32 "                \
        "{%0,%1,%2,%3}, {%4,%5,%6,%7}, {%8,%9}, {%0,%1,%2,%3};"             \
        : "+f"(c[0]), "+f"(c[1]), "+f"(c[2]), "+f"(c[3])                    \
        : "r"(a[0]), "r"(a[1]), "r"(a[2]), "r"(a[3]), "r"(b0), "r"(b1))

__device__ __forceinline__ void cp_async16(uint32_t saddr, const void* gptr) {
    asm volatile("cp.async.cg.shared.global [%0], [%1], 16;\n" :: "r"(saddr), "l"(gptr));
}
__device__ __forceinline__ void cp_commit() { asm volatile("cp.async.commit_group;\n"); }

__device__ __forceinline__ unsigned pack_h2(float2 p) {
    __half2 h = __float22half2_rn(p);
    return *(unsigned*)&h;
}

static constexpr int stage2(int BN, int asz, int bsz) {
    return 128 * ((asz == 2) ? HROW : SROW) * asz + BN * ((bsz == 2) ? HROW : SROW) * bsz;
}

// ========== unified GEMM: A f32/f16, B f32/f16 (fp16 MMA; BM=128; BN=64/128) ==========
template <int BN, typename AT, typename BT, typename OutT>
__global__ void __launch_bounds__(256) gemm_f16(
    const AT* __restrict__ A, int lda,
    const BT* __restrict__ Bm, int ldb,
    const float* __restrict__ bias,
    const float* __restrict__ Csrc, int ldsrc,
    OutT* __restrict__ Cbase, int ldc, size_t zstride,
    int N, int K) {
    constexpr bool AH = (sizeof(AT) == 2);
    constexpr bool BH = (sizeof(BT) == 2);
    constexpr int ABYTES = 128 * (AH ? HROW : SROW) * (int)sizeof(AT);
    constexpr int BBYTES = BN * (BH ? HROW : SROW) * (int)sizeof(BT);
    constexpr int STB = ABYTES + BBYTES;
    constexpr int NI = BN / 16;
    extern __shared__ char smem[];
    const int tid = threadIdx.x;
    const int m0 = blockIdx.y * 128;
    const int n0 = blockIdx.x * BN;
    const int Koff = blockIdx.z * K;
    OutT* C = Cbase + (size_t)blockIdx.z * zstride;
    const bool final_z = (gridDim.z == 1);

    const int warp = tid >> 5, lane = tid & 31;
    const int g = lane >> 2, tg = lane & 3;
    const int wm = (warp >> 1) * 32;
    const int wn = (warp & 1) * (BN / 2);

    float acc[2][NI][4];
#pragma unroll
    for (int mi = 0; mi < 2; mi++)
#pragma unroll
        for (int ni = 0; ni < NI; ni++)
#pragma unroll
            for (int j = 0; j < 4; j++) acc[mi][ni][j] = 0.f;

    const int ntiles = K >> 5;

    auto load_stage = [&](int buf, int kt) {
        char* base = smem + buf * STB;
        const int kb = Koff + kt;
        if (AH) {
            __half* sA = (__half*)base;
#pragma unroll
            for (int i = 0; i < 2; i++) {
                int idx = tid + i * 256;
                int row = idx >> 2;
                int q = (idx & 3) * 8;
                uint32_t d = (uint32_t)__cvta_generic_to_shared(sA + row * HROW + q);
                cp_async16(d, (const __half*)A + (size_t)(m0 + row) * lda + kb + q);
            }
        } else {
            float* sA = (float*)base;
#pragma unroll
            for (int i = 0; i < 4; i++) {
                int idx = tid + i * 256;
                int row = idx >> 3;
                int q = (idx & 7) << 2;
                uint32_t d = (uint32_t)__cvta_generic_to_shared(sA + row * SROW + q);
                cp_async16(d, (const float*)A + (size_t)(m0 + row) * lda + kb + q);
            }
        }
        if (BH) {
            __half* sB = (__half*)(base + ABYTES);
#pragma unroll
            for (int i = 0; i < BN / 64; i++) {
                int idx = tid + i * 256;
                int row = idx >> 2;
                int q = (idx & 3) * 8;
                int nr = n0 + row;
                if (nr >= N) nr = N - 1;
                uint32_t d = (uint32_t)__cvta_generic_to_shared(sB + row * HROW + q);
                cp_async16(d, (const __half*)Bm + (size_t)nr * ldb + kb + q);
            }
        } else {
            float* sB = (float*)(base + ABYTES);
#pragma unroll
            for (int i = 0; i < BN / 32; i++) {
                int idx = tid + i * 256;
                int row = idx >> 3;
                int q = (idx & 7) << 2;
                int nr = n0 + row;
                if (nr >= N) nr = N - 1;
                uint32_t d = (uint32_t)__cvta_generic_to_shared(sB + row * SROW + q);
                cp_async16(d, (const float*)Bm + (size_t)nr * ldb + kb + q);
            }
        }
        cp_commit();
    };

    load_stage(0, 0);

    for (int kt = 0; kt < ntiles; kt++) {
        if (kt + 1 < ntiles) {
            load_stage((kt + 1) & 1, (kt + 1) << 5);
            asm volatile("cp.async.wait_group 1;\n");
        } else {
            asm volatile("cp.async.wait_group 0;\n");
        }
        __syncthreads();

        const char* base = smem + (kt & 1) * STB;

#pragma unroll
        for (int ks = 0; ks < 2; ks++) {
            const int k0 = ks * 16;
            unsigned ah[2][4];
            if (AH) {
                const __half* sAh = (const __half*)base;
#pragma unroll
                for (int mi = 0; mi < 2; mi++) {
                    int r = wm + mi * 16;
                    ah[mi][0] = *(const unsigned*)&sAh[(r + g) * HROW + k0 + 2 * tg];
                    ah[mi][1] = *(const unsigned*)&sAh[(r + g + 8) * HROW + k0 + 2 * tg];
                    ah[mi][2] = *(const unsigned*)&sAh[(r + g) * HROW + k0 + 8 + 2 * tg];
                    ah[mi][3] = *(const unsigned*)&sAh[(r + g + 8) * HROW + k0 + 8 + 2 * tg];
                }
            } else {
                const float* sAf = (const float*)base;
#pragma unroll
                for (int mi = 0; mi < 2; mi++) {
                    int r = wm + mi * 16;
                    ah[mi][0] = pack_h2(*(const float2*)&sAf[(r + g) * SROW + k0 + 2 * tg]);
                    ah[mi][1] = pack_h2(*(const float2*)&sAf[(r + g + 8) * SROW + k0 + 2 * tg]);
                    ah[mi][2] = pack_h2(*(const float2*)&sAf[(r + g) * SROW + k0 + 8 + 2 * tg]);
                    ah[mi][3] = pack_h2(*(const float2*)&sAf[(r + g + 8) * SROW + k0 + 8 + 2 * tg]);
                }
            }
#pragma unroll
            for (int ni = 0; ni < NI; ni++) {
                int cb = wn + ni * 8;
                unsigned b0, b1;
                if (BH) {
                    const __half* sBh = (const __half*)(base + ABYTES);
                    b0 = *(const unsigned*)&sBh[(cb + g) * HROW + k0 + 2 * tg];
                    b1 = *(const unsigned*)&sBh[(cb + g) * HROW + k0 + 8 + 2 * tg];
                } else {
                    const float* sBf = (const float*)(base + ABYTES);
                    b0 = pack_h2(*(const float2*)&sBf[(cb + g) * SROW + k0 + 2 * tg]);
                    b1 = pack_h2(*(const float2*)&sBf[(cb + g) * SROW + k0 + 8 + 2 * tg]);
                }
#pragma unroll
                for (int mi = 0; mi < 2; mi++) MMA_F16(acc[mi][ni], ah[mi], b0, b1);
            }
        }
        __syncthreads();
    }

#pragma unroll
    for (int mi = 0; mi < 2; mi++) {
#pragma unroll
        for (int ni = 0; ni < NI; ni++) {
            int r0 = m0 + wm + mi * 16 + g;
            int c0 = n0 + wn + ni * 8 + tg * 2;
#pragma unroll
            for (int half = 0; half < 2; half++) {
                int rr = r0 + half * 8;
#pragma unroll
                for (int j = 0; j < 2; j++) {
                    int cc = c0 + j;
                    if (cc >= N) continue;
                    float v = acc[mi][ni][half * 2 + j];
                    if (final_z) {
                        if (bias) v += bias[cc];
                        if (Csrc) v += Csrc[(size_t)rr * ldsrc + cc];
                    }
                    C[(size_t)rr * ldc + cc] = (OutT)v;
                }
            }
        }
    }
}

// ---------------- small kernels ----------------
__global__ void bsum_kernel(float* __restrict__ out, const float* __restrict__ a,
                            const float* __restrict__ b) {
    int i = blockIdx.x * blockDim.x + threadIdx.x;
    if (i < 2048) out[i] = a[i] + b[i];
}

__global__ void f2h_kernel(const float* __restrict__ in, __half* __restrict__ out, int n) {
    int i = (blockIdx.x * blockDim.x + threadIdx.x) * 4;
    if (i >= n) return;
    float4 v = *(const float4*)(in + i);
    __half2 h0 = __float22half2_rn(make_float2(v.x, v.y));
    __half2 h1 = __float22half2_rn(make_float2(v.z, v.w));
    uint2 p;
    p.x = *(unsigned*)&h0;
    p.y = *(unsigned*)&h1;
    *(uint2*)(out + i) = p;
}

__global__ void gather_kernel(const int* __restrict__ cap, const float* __restrict__ table,
                              __half* __restrict__ E) {
    int bt = blockIdx.x;
    int b = bt / TSTEPS, tt = bt % TSTEPS;
    int idx = cap[b * (TSTEPS + 1) + tt];
    float4 v = ((const float4*)(table + (size_t)idx * EMBD))[threadIdx.x];
    __half2 h0 = __float22half2_rn(make_float2(v.x, v.y));
    __half2 h1 = __float22half2_rn(make_float2(v.z, v.w));
    uint2 p;
    p.x = *(unsigned*)&h0;
    p.y = *(unsigned*)&h1;
    *(uint2*)(E + (size_t)bt * EMBD + threadIdx.x * 4) = p;
}

__global__ void prep_enc_kernel(const float* __restrict__ enc, __half* __restrict__ ench,
                                float* __restrict__ mean) {
    int b = blockIdx.y;
    int e = blockIdx.x * 256 + threadIdx.x;
    const float* ep = enc + (size_t)b * RR * ENCD + e;
    __half* op = ench + (size_t)b * RR * ENCD + e;
    float acc = 0.f;
#pragma unroll 4
    for (int r = 0; r < RR; r++) {
        float v = ep[(size_t)r * ENCD];
        acc += v;
        op[(size_t)r * ENCD] = __float2half_rn(v);
    }
    mean[b * ENCD + e] = acc * (1.f / (float)RR);
}

// ============ fused attention + softmax + context (one block per b) ============
__global__ void __launch_bounds__(1024) att_ctx_kernel(
    const __half* __restrict__ att1h, const __half* __restrict__ ench,
    const float* __restrict__ hproj,
    const float* __restrict__ wfull, const float* __restrict__ bfull,
    __half* __restrict__ ctxh, float* __restrict__ out_alpha, int t) {
    int b = blockIdx.x;
    int tid = threadIdx.x;  // 1024
    int warp = tid >> 5, lane = tid & 31;
    __shared__ float s_att2[512], s_wf[512], s_sc[RR], s_red[32];
    __shared__ float s_part[4][2048];
    if (tid < 512) {
        s_att2[tid] = hproj[b * 4608 + tid];
        s_wf[tid] = wfull[tid];
    }
    __syncthreads();

    float bf = bfull[0];
    for (int r = warp; r < RR; r += 32) {
        const float4* ap = (const float4*)(att1h + (size_t)(b * RR + r) * ATTD);
        float s = 0.f;
#pragma unroll
        for (int i = 0; i < 2; i++) {
            float4 v = ap[lane + i * 32];
            const __half2* hv = (const __half2*)&v;
            int a = (lane + i * 32) * 8;
#pragma unroll
            for (int j = 0; j < 4; j++) {
                float2 f = __half22float2(hv[j]);
                s += fmaxf(f.x + s_att2[a + 2 * j], 0.f) * s_wf[a + 2 * j]
                   + fmaxf(f.y + s_att2[a + 2 * j + 1], 0.f) * s_wf[a + 2 * j + 1];
            }
        }
#pragma unroll
        for (int o = 16; o; o >>= 1) s += __shfl_xor_sync(0xffffffffu, s, o);
        if (lane == 0) s_sc[r] = s + bf;
    }
    __syncthreads();

    float m = (tid < RR) ? s_sc[tid] : -1e30f;
#pragma unroll
    for (int o = 16; o; o >>= 1) m = fmaxf(m, __shfl_xor_sync(0xffffffffu, m, o));
    if (lane == 0) s_red[warp] = m;
    __syncthreads();
    m = s_red[0];
#pragma unroll
    for (int w = 1; w < 32; w++) m = fmaxf(m, s_red[w]);
    __syncthreads();
    float sum = 0.f;
    if (tid < RR) {
        float e = expf(s_sc[tid] - m);
        s_sc[tid] = e;
        sum = e;
    }
#pragma unroll
    for (int o = 16; o; o >>= 1) sum += __shfl_xor_sync(0xffffffffu, sum, o);
    if (lane == 0) s_red[warp] = sum;
    __syncthreads();
    sum = 0.f;
#pragma unroll
    for (int w = 0; w < 32; w++) sum += s_red[w];
    float inv = 1.f / sum;
    if (tid < RR) out_alpha[((size_t)b * TSTEPS + t) * RR + tid] = s_sc[tid] * inv;
    __syncthreads();

    {
        int rg = tid >> 8;
        int et = tid & 255;
        const float4* ep4 = (const float4*)(ench + (size_t)b * RR * ENCD) + et;
        float a8[8];
#pragma unroll
        for (int j = 0; j < 8; j++) a8[j] = 0.f;
#pragma unroll 4
        for (int r = rg; r < RR; r += 4) {
            float4 v = ep4[(size_t)r * 256];
            const __half2* hv = (const __half2*)&v;
            float a = s_sc[r];
#pragma unroll
            for (int j = 0; j < 4; j++) {
                float2 f = __half22float2(hv[j]);
                a8[2 * j] += a * f.x;
                a8[2 * j + 1] += a * f.y;
            }
        }
#pragma unroll
        for (int j = 0; j < 8; j++) s_part[rg][et * 8 + j] = a8[j];
    }
    __syncthreads();

    {
        int e = tid * 2;
        float v0 = (s_part[0][e] + s_part[1][e]) + (s_part[2][e] + s_part[3][e]);
        float v1 = (s_part[0][e + 1] + s_part[1][e + 1]) + (s_part[2][e + 1] + s_part[3][e + 1]);
        v0 *= inv;
        v1 *= inv;
        float g0 = hproj[b * 4608 + 512 + e];
        float g1 = hproj[b * 4608 + 512 + e + 1];
        v0 /= (1.f + expf(-g0));
        v1 /= (1.f + expf(-g1));
        *(__half2*)&ctxh[b * ENCD + e] = __floats2half2_rn(v0, v1);
    }
}

// split-K reduce + (embproj + hWhh) + LSTM pointwise; writes fp32 state + fp16 Hh
__global__ void lstm_kernel(const float* __restrict__ gpart, const float* __restrict__ embproj,
                            const float* __restrict__ hproj,
                            float* __restrict__ state, __half* __restrict__ Hh, int t) {
    int b = blockIdx.x, d = threadIdx.x;  // 512 threads
    float gt[4];
#pragma unroll
    for (int q = 0; q < 4; q++) {
        int j = b * 2048 + q * 512 + d;
        float s = embproj[((size_t)b * TSTEPS + t) * 2048 + q * 512 + d]
                + hproj[b * 4608 + 2560 + q * 512 + d];
#pragma unroll
        for (int z = 0; z < 4; z++) s += gpart[z * BATCH * 2048 + j];
        gt[q] = s;
    }
    float i_ = 1.f / (1.f + expf(-gt[0]));
    float f_ = 1.f / (1.f + expf(-gt[1]));
    float g_ = tanhf(gt[2]);
    float o_ = 1.f / (1.f + expf(-gt[3]));
    float c = state[b * 1024 + 512 + d];
    float cn = f_ * c + i_ * g_;
    float hn = o_ * tanhf(cn);
    state[b * 1024 + d] = hn;
    state[b * 1024 + 512 + d] = cn;
    Hh[((size_t)b * TSTEPS + t) * DECD + d] = __float2half_rn(hn);
}

// ---------------- host ----------------
static float* symaddr(const void* sym) {
    void* p = nullptr;
    cudaGetSymbolAddress(&p, sym);
    return (float*)p;
}

template <int BN, typename AT, typename BT, typename OutT>
static void launch_g(cudaStream_t st, const AT* A, int lda, const BT* B, int ldb,
                     const float* bias, const float* Csrc, int ldsrc,
                     OutT* C, int ldc, size_t zstride,
                     int M, int N, int K, int zsplit) {
    dim3 grid((N + BN - 1) / BN, M / 128, zsplit);
    int smem = 2 * stage2(BN, (int)sizeof(AT), (int)sizeof(BT));
    cudaFuncSetAttribute((const void*)gemm_f16<BN, AT, BT, OutT>,
                         cudaFuncAttributeMaxDynamicSharedMemorySize, smem);
    gemm_f16<BN, AT, BT, OutT><<<grid, 256, smem, st>>>(A, lda, B, ldb, bias, Csrc, ldsrc,
                                                        C, ldc, zstride, N, K / zsplit);
}

static void f2h(const float* in, __half* out, size_t n) {
    f2h_kernel<<<(unsigned)((n / 4 + 255) / 256), 256>>>(in, out, (int)n);
}

extern "C" void kernel_launch(void* const* d_in, const int* in_sizes, int n_in,
                              void* d_out, int out_size) {
    const float* enc       = (const float*)d_in[0];
    const int*   captions  = (const int*)d_in[1];
    const float* W_enc_att = (const float*)d_in[2];
    const float* b_enc_att = (const float*)d_in[3];
    const float* W_dec_att = (const float*)d_in[4];
    const float* b_dec_att = (const float*)d_in[5];
    const float* W_full    = (const float*)d_in[6];
    const float* b_full    = (const float*)d_in[7];
    const float* emb_table = (const float*)d_in[8];
    const float* W_ih      = (const float*)d_in[9];
    const float* W_hh      = (const float*)d_in[10];
    const float* b_ih      = (const float*)d_in[11];
    const float* b_hh      = (const float*)d_in[12];
    const float* W_init_h  = (const float*)d_in[13];
    const float* b_init_h  = (const float*)d_in[14];
    const float* W_init_c  = (const float*)d_in[15];
    const float* b_init_c  = (const float*)d_in[16];
    const float* W_fbeta   = (const float*)d_in[17];
    const float* b_fbeta   = (const float*)d_in[18];
    const float* W_fc      = (const float*)d_in[19];
    const float* b_fc      = (const float*)d_in[20];

    float* out_pred  = (float*)d_out;
    float* out_alpha = out_pred + (size_t)BATCH * TSTEPS * VOC;

    __half* att1h = (__half*)symaddr(g_att1h);
    __half* ench  = (__half*)symaddr(g_ench);
    __half* ctxh  = (__half*)symaddr(g_ctxh);
    __half* Hh    = (__half*)symaddr(g_Hh);
    __half* Eh    = (__half*)symaddr(g_Eh);
    float* meanb  = symaddr(g_mean);
    float* state  = symaddr(g_state);
    float* hproj  = symaddr(g_hproj);
    float* gpart  = symaddr(g_gpart);
    float* embprj = symaddr(g_embproj);
    float* Wcat   = symaddr(g_Wcat);
    float* bcat   = symaddr(g_bcat);
    float* bsum   = symaddr(g_bsum);
    float* Winit  = symaddr(g_Winit);
    float* binit  = symaddr(g_binit);
    __half* Wcat_h  = (__half*)symaddr(g_Wcat_h);
    __half* Wih_h   = (__half*)symaddr(g_Wih_h);
    __half* Wfc_h   = (__half*)symaddr(g_Wfc_h);
    __half* Wenc_h  = (__half*)symaddr(g_Wenc_h);
    __half* Winit_h = (__half*)symaddr(g_Winit_h);

    // persistent stream + events (created once, outside capture; no device mem alloc)
    static cudaStream_t s2 = nullptr;
    static cudaEvent_t evs[TSTEPS + 3];
    if (!s2) {
        cudaStreamCreate(&s2);
        for (int i = 0; i < TSTEPS + 3; i++)
            cudaEventCreateWithFlags(&evs[i], cudaEventDisableTiming);
    }
    cudaEvent_t evPre = evs[TSTEPS];      // prologue fork
    cudaEvent_t evAtt = evs[TSTEPS + 1];  // att1 join
    cudaEvent_t evFin = evs[TSTEPS + 2];  // final fc join

    // ---- prologue: weight concats (stream 0) ----
    cudaMemcpyAsync(Wcat, W_dec_att, (size_t)512 * 512 * 4, cudaMemcpyDeviceToDevice, 0);
    cudaMemcpyAsync(Wcat + 512 * 512, W_fbeta, (size_t)2048 * 512 * 4, cudaMemcpyDeviceToDevice, 0);
    cudaMemcpyAsync(Wcat + 2560 * 512, W_hh, (size_t)2048 * 512 * 4, cudaMemcpyDeviceToDevice, 0);
    cudaMemcpyAsync(bcat, b_dec_att, 512 * 4, cudaMemcpyDeviceToDevice, 0);
    cudaMemcpyAsync(bcat + 512, b_fbeta, 2048 * 4, cudaMemcpyDeviceToDevice, 0);
    cudaMemsetAsync(bcat + 2560, 0, 2048 * 4, 0);
    cudaMemcpyAsync(Winit, W_init_h, (size_t)512 * 2048 * 4, cudaMemcpyDeviceToDevice, 0);
    cudaMemcpyAsync(Winit + (size_t)512 * 2048, W_init_c, (size_t)512 * 2048 * 4,
                    cudaMemcpyDeviceToDevice, 0);
    cudaMemcpyAsync(binit, b_init_h, 512 * 4, cudaMemcpyDeviceToDevice, 0);
    cudaMemcpyAsync(binit + 512, b_init_c, 512 * 4, cudaMemcpyDeviceToDevice, 0);

    // fp16 weight mirrors
    f2h(Wcat, Wcat_h, (size_t)4608 * 512);
    f2h(W_ih, Wih_h, (size_t)2048 * 2560);
    f2h(W_fc, Wfc_h, (size_t)VOC * 512);
    f2h(W_enc_att, Wenc_h, (size_t)512 * 2048);
    f2h(Winit, Winit_h, (size_t)1024 * 2048);

    bsum_kernel<<<8, 256>>>(bsum, b_ih, b_hh);
    prep_enc_kernel<<<dim3(8, BATCH), 256>>>(enc, ench, meanb);
    cudaEventRecord(evPre, 0);

    // fork: att1 GEMM on s2 (needs ench + Wenc_h, both ready at evPre)
    cudaStreamWaitEvent(s2, evPre, 0);
    launch_g<128, __half, __half, __half>(s2, ench, ENCD, Wenc_h, ENCD, b_enc_att, nullptr, 0,
                                          att1h, ATTD, 0, BATCH * RR, ATTD, ENCD, 1);
    cudaEventRecord(evAtt, s2);

    // stream 0 meanwhile: init GEMM + gather + embproj
    launch_g<64, float, __half, float>(0, meanb, ENCD, Winit_h, ENCD, binit, nullptr, 0,
                                       state, 1024, 0, BATCH, 1024, ENCD, 1);
    gather_kernel<<<BATCH * TSTEPS, 128>>>(captions, emb_table, Eh);
    launch_g<128, __half, __half, float>(0, Eh, EMBD, Wih_h, EMBD + ENCD, bsum, nullptr, 0,
                                         embprj, 2048, 0, BATCH * TSTEPS, 2048, EMBD, 1);
    cudaStreamWaitEvent(0, evAtt, 0);   // join att1 before the loop's att_ctx

    // ---- recurrence; fc slices overlapped on s2 ----
    for (int t = 0; t < TSTEPS; t++) {
        launch_g<64, float, __half, float>(0, state, 1024, Wcat_h, 512, bcat, nullptr, 0,
                                           hproj, 4608, 0, BATCH, 4608, DECD, 1);
        att_ctx_kernel<<<BATCH, 1024>>>(att1h, ench, hproj, W_full, b_full,
                                        ctxh, out_alpha, t);
        launch_g<64, __half, __half, float>(0, ctxh, ENCD, Wih_h + 512, EMBD + ENCD, nullptr,
                                            nullptr, 0, gpart, 2048, (size_t)BATCH * 2048,
                                            BATCH, 2048, ENCD, 4);
        lstm_kernel<<<BATCH, 512>>>(gpart, embprj, hproj, state, Hh, t);
        cudaEventRecord(evs[t], 0);
        // fc slice for step t: A rows strided (lda = TSTEPS*DECD), C cols at t*VOC
        cudaStreamWaitEvent(s2, evs[t], 0);
        launch_g<128, __half, __half, float>(s2, Hh + (size_t)t * DECD, TSTEPS * DECD,
                                             Wfc_h, DECD, b_fc, nullptr, 0,
                                             out_pred + (size_t)t * VOC, TSTEPS * VOC, 0,
                                             BATCH, VOC, DECD, 1);
    }

    // join fc stream back
    cudaEventRecord(evFin, s2);
    cudaStreamWaitEvent(0, evFin, 0);
}